// round 13
// baseline (speedup 1.0000x reference)
#include <cuda_runtime.h>
#include <cuda_bf16.h>
#include <math.h>
#include <stdint.h>

#define BB 4
#define DM 1024
#define SS 2048
#define HH 16
#define HD 64
#define K2 2048   // GEMM rows: [hi x1024 | lo x1024]
#define AK2 128   // attention rows: [hi x64 | lo x64]

// ---------------- scratch (device globals; allocation-free) ----------------
__device__ __nv_bfloat16 g_xTbig[(size_t)BB * SS * K2];
__device__ __nv_bfloat16 g_Wqkv[(size_t)3 * DM * K2];  // [Wq ; Wk ; Wv] split rows
__device__ __nv_bfloat16 g_Wob[(size_t)DM * K2];
__device__ __nv_bfloat16 g_Qs[(size_t)BB * HH * SS * AK2];  // [qh|ql] x(log2e/8)
__device__ __nv_bfloat16 g_Ks[(size_t)BB * HH * SS * AK2];  // [kh|kl]
__device__ __nv_bfloat16 g_Vt[(size_t)BB * HH * 32 * HD * AK2]; // V^T [vh|vl]
__device__ __nv_bfloat16 g_attbig[(size_t)BB * SS * K2];

// ---------------- helpers ----------------
__device__ __forceinline__ uint32_t smem_u32(const void* p) {
    uint32_t a;
    asm("{ .reg .u64 t; cvta.to.shared.u64 t, %1; cvt.u32.u64 %0, t; }" : "=r"(a) : "l"(p));
    return a;
}
__device__ __forceinline__ void cp16(uint32_t s, const void* g) {
    asm volatile("cp.async.cg.shared.global [%0], [%1], 16;" :: "r"(s), "l"(g) : "memory");
}
#define CP_COMMIT() asm volatile("cp.async.commit_group;" ::: "memory")
#define CP_WAIT1()  asm volatile("cp.async.wait_group 1;" ::: "memory")
#define CP_WAIT0()  asm volatile("cp.async.wait_group 0;" ::: "memory")

__device__ __forceinline__ void ldsm4(uint32_t* r, uint32_t addr) {
    asm volatile("ldmatrix.sync.aligned.m8n8.x4.shared.b16 {%0,%1,%2,%3}, [%4];"
                 : "=r"(r[0]), "=r"(r[1]), "=r"(r[2]), "=r"(r[3]) : "r"(addr));
}
__device__ __forceinline__ void mma16816(float* c, const uint32_t* a,
                                         uint32_t b0, uint32_t b1) {
    asm volatile("mma.sync.aligned.m16n8k16.row.col.f32.bf16.bf16.f32 "
                 "{%0,%1,%2,%3}, {%4,%5,%6,%7}, {%8,%9}, {%0,%1,%2,%3};"
                 : "+f"(c[0]), "+f"(c[1]), "+f"(c[2]), "+f"(c[3])
                 : "r"(a[0]), "r"(a[1]), "r"(a[2]), "r"(a[3]), "r"(b0), "r"(b1));
}
__device__ __forceinline__ float ex2(float x) {
    float y;
    asm("ex2.approx.f32 %0, %1;" : "=f"(y) : "f"(x));
    return y;
}
// round-based split (scalar prep kernels)
__device__ __forceinline__ void split2(float v, __nv_bfloat16& hi, __nv_bfloat16& lo) {
    hi = __float2bfloat16(v);
    lo = __float2bfloat16(v - __bfloat162float(hi));
}
// cheap truncation split (hot paths)
__device__ __forceinline__ uint32_t packhi(float a, float b) {
    return __byte_perm(__float_as_uint(a), __float_as_uint(b), 0x7632);
}
__device__ __forceinline__ float lopart(float v) {
    return v - __uint_as_float(__float_as_uint(v) & 0xFFFF0000u);
}
__device__ __forceinline__ uint32_t packlo2(float l0, float l1) {
    uint32_t r;
    asm("cvt.rn.bf16x2.f32 %0, %1, %2;" : "=r"(r) : "f"(l1), "f"(l0));
    return r;
}

// ---------------------------------------------------------------------------
// Kernel 1: x[B,D,S] + PE -> xTbig rows [ah | al]
// ---------------------------------------------------------------------------
__global__ void pe_transpose_split(const float* __restrict__ x,
                                   __nv_bfloat16* __restrict__ out) {
    __shared__ float tile[32][33];
    int b = blockIdx.z;
    int d0 = blockIdx.y * 32, s0 = blockIdx.x * 32;
    int d = d0 + threadIdx.y, s = s0 + threadIdx.x;
    float denom = expf((float)(d & ~1) * (-9.210340371976184f / (float)DM));
    float ang = (float)s * denom;
    float pe = (d & 1) ? cosf(ang) : sinf(ang);
    tile[threadIdx.y][threadIdx.x] = x[((size_t)b * DM + d) * SS + s] + pe;
    __syncthreads();
    int s2 = s0 + threadIdx.y, d2 = d0 + threadIdx.x;
    float v = tile[threadIdx.x][threadIdx.y];
    __nv_bfloat16 hi, lo; split2(v, hi, lo);
    size_t base = ((size_t)b * SS + s2) * K2;
    out[base + d2] = hi;
    out[base + 1024 + d2] = lo;
}

// ---------------------------------------------------------------------------
// Kernel 1b: weight split -> rows [wh | wl]; Wq,Wk,Wv into one buffer
// ---------------------------------------------------------------------------
__global__ void wsplit_kernel(const float* __restrict__ w0, const float* __restrict__ w1,
                              const float* __restrict__ w2, const float* __restrict__ w3,
                              __nv_bfloat16* oqkv, __nv_bfloat16* oo) {
    const float* src; __nv_bfloat16* dst;
    switch (blockIdx.y) {
        case 0: src = w0; dst = oqkv; break;
        case 1: src = w1; dst = oqkv + (size_t)DM * K2; break;
        case 2: src = w2; dst = oqkv + (size_t)2 * DM * K2; break;
        default: src = w3; dst = oo; break;
    }
    int idx = blockIdx.x * 256 + threadIdx.x;
    int n = idx >> 10, dcol = idx & 1023;
    __nv_bfloat16 hi, lo; split2(src[idx], hi, lo);
    size_t base = (size_t)n * K2;
    dst[base + dcol] = hi;
    dst[base + 1024 + dcol] = lo;
}

// ---------------------------------------------------------------------------
// Kernel 2: HMMA GEMM (unchanged mainloop; MODE 0 fused QKV, MODE 3 final)
// ---------------------------------------------------------------------------
#define STG 40960
#define GEMM_SMEM 81920
#define QSCALE 0.18033688011112042f  // 0.125 * log2(e)

template <int MODE>
__global__ __launch_bounds__(256, 2)
void hmma_gemm(const __nv_bfloat16* __restrict__ A, const __nv_bfloat16* __restrict__ W,
               const float* __restrict__ bias, const float* __restrict__ bias2,
               const float* __restrict__ bias3,
               void* __restrict__ outv, void* __restrict__ outv2,
               void* __restrict__ outv3) {
    extern __shared__ char smem[];
    const uint32_t sb = smem_u32(smem);
    const int tid = threadIdx.x, wid = tid >> 5, lane = tid & 31;
    const int wr = wid >> 1, wc = wid & 1;
    const int mBase = blockIdx.y * 128, nBase = blockIdx.x * 128;

    float acc[2][8][4];
#pragma unroll
    for (int i = 0; i < 2; i++)
#pragma unroll
        for (int j = 0; j < 8; j++)
#pragma unroll
            for (int r = 0; r < 4; r++) acc[i][j][r] = 0.f;

    const int r0 = tid >> 2, c4 = tid & 3;
    const __nv_bfloat16* gA = A + (size_t)(mBase + r0) * K2 + c4 * 8;
    const __nv_bfloat16* gW = W + (size_t)(nBase + r0) * K2 + c4 * 8;

#define LOAD_CHUNK(c, st)                                                     \
    do {                                                                      \
        uint32_t s0 = sb + (st) * STG + r0 * 80 + c4 * 16;                    \
        cp16(s0,                 gA + (c) * 32);                              \
        cp16(s0 + 64 * 80,       gA + (size_t)64 * K2 + (c) * 32);            \
        cp16(s0 + 10240,         gA + 1024 + (c) * 32);                       \
        cp16(s0 + 10240 + 64*80, gA + (size_t)64 * K2 + 1024 + (c) * 32);     \
        cp16(s0 + 20480,         gW + (c) * 32);                              \
        cp16(s0 + 20480 + 64*80, gW + (size_t)64 * K2 + (c) * 32);            \
        cp16(s0 + 30720,         gW + 1024 + (c) * 32);                       \
        cp16(s0 + 30720 + 64*80, gW + (size_t)64 * K2 + 1024 + (c) * 32);     \
        CP_COMMIT();                                                          \
    } while (0)

    LOAD_CHUNK(0, 0);
    LOAD_CHUNK(1, 1);

    const uint32_t aB = (wr * 32 + (lane & 15)) * 80 + (lane >> 4) * 16;
    const uint32_t bB = 20480 + (wc * 64 + (lane & 15)) * 80 + (lane >> 4) * 16;

    const int NCH = 1024 / 32;  // 32
    for (int c = 0; c < NCH; c++) {
        if (c == NCH - 1) CP_WAIT0(); else CP_WAIT1();
        __syncthreads();
        const uint32_t stg = sb + (c & 1) * STG;
#pragma unroll
        for (int ks = 0; ks < 2; ks++) {
            uint32_t ah[2][4], al[2][4], bh[4][4], bl[4][4];
            ldsm4(ah[0], stg + aB + ks * 32);
            ldsm4(ah[1], stg + aB + 16 * 80 + ks * 32);
            ldsm4(al[0], stg + aB + 10240 + ks * 32);
            ldsm4(al[1], stg + aB + 10240 + 16 * 80 + ks * 32);
#pragma unroll
            for (int j2 = 0; j2 < 4; j2++) {
                ldsm4(bh[j2], stg + bB + j2 * 16 * 80 + ks * 32);
                ldsm4(bl[j2], stg + bB + 10240 + j2 * 16 * 80 + ks * 32);
            }
#pragma unroll
            for (int mi = 0; mi < 2; mi++)
#pragma unroll
                for (int nj = 0; nj < 8; nj++) {
                    uint32_t b0 = bh[nj >> 1][nj & 1], b1 = bh[nj >> 1][(nj & 1) + 2];
                    mma16816(acc[mi][nj], ah[mi], b0, b1);
                    mma16816(acc[mi][nj], al[mi], b0, b1);
                    mma16816(acc[mi][nj], ah[mi],
                             bl[nj >> 1][nj & 1], bl[nj >> 1][(nj & 1) + 2]);
                }
        }
        __syncthreads();
        if (c + 2 < NCH) LOAD_CHUNK(c + 2, c & 1);
    }
#undef LOAD_CHUNK

    __syncthreads();
    float* ep = (float*)smem;
#pragma unroll
    for (int mi = 0; mi < 2; mi++)
#pragma unroll
        for (int nj = 0; nj < 8; nj++) {
            int row = wr * 32 + mi * 16 + (lane >> 2);
            int col = wc * 64 + nj * 8 + (lane & 3) * 2;
            ep[row * 129 + col] = acc[mi][nj][0];
            ep[row * 129 + col + 1] = acc[mi][nj][1];
            ep[(row + 8) * 129 + col] = acc[mi][nj][2];
            ep[(row + 8) * 129 + col + 1] = acc[mi][nj][3];
        }
    __syncthreads();

    if (MODE == 3) {
        float* out = (float*)outv;
        int nl = tid >> 1;
        int n = nBase + nl;
        float bn = bias[n];
#pragma unroll
        for (int ii = 0; ii < 16; ii++) {
            int sl = (tid & 1) * 64 + ii * 4;
            int m0 = mBase + sl, b = m0 >> 11, s = m0 & 2047;
            float4 v;
            v.x = ep[(sl + 0) * 129 + nl] + bn;
            v.y = ep[(sl + 1) * 129 + nl] + bn;
            v.z = ep[(sl + 2) * 129 + nl] + bn;
            v.w = ep[(sl + 3) * 129 + nl] + bn;
            *(float4*)&out[((size_t)b * DM + n) * SS + s] = v;
        }
    } else if (nBase >= 2048) {
        // V^T: [bh, chunk, d, [vh64|vl64]]; coalesced uint4 stores.
        __nv_bfloat16* out = (__nv_bfloat16*)outv3;
        int b = mBase >> 11, s0 = mBase & 2047;
#pragma unroll
        for (int it = 0; it < 8; it++) {
            int t = tid + it * 256;
            int dl = t >> 4;
            int rem = t & 15;
            int ch = rem >> 3, jb = (rem & 7) * 8;
            int n = nBase - 2048 + dl;
            int h = n >> 6, dd = n & 63;
            float bn = bias3[n];
            size_t vb = (((size_t)(b * HH + h)) * 32 + (s0 >> 6) + ch) * (64 * AK2)
                        + (size_t)dd * AK2;
            uint32_t hp[4], lp[4];
#pragma unroll
            for (int j2 = 0; j2 < 4; j2++) {
                float v0 = ep[(ch * 64 + jb + 2 * j2) * 129 + dl] + bn;
                float v1 = ep[(ch * 64 + jb + 2 * j2 + 1) * 129 + dl] + bn;
                hp[j2] = packhi(v0, v1);
                lp[j2] = packlo2(lopart(v0), lopart(v1));
            }
            *(uint4*)&out[vb + jb] = *(uint4*)&hp[0];
            *(uint4*)&out[vb + 64 + jb] = *(uint4*)&lp[0];
        }
    } else {
        // Q (nBase<1024, xQSCALE) / K: rows [hi64|lo64]
        const bool isQ = (nBase < 1024);
        __nv_bfloat16* out = isQ ? (__nv_bfloat16*)outv : (__nv_bfloat16*)outv2;
        const float* bi = isQ ? bias : bias2;
        const int nOff = isQ ? nBase : nBase - 1024;
        const float sc = isQ ? QSCALE : 1.0f;
#pragma unroll
        for (int i = 0; i < 8; i++) {
            int r = (tid >> 4) + i * 16;
            int cc = (tid & 15) * 8;
            int m = mBase + r, b = m >> 11, s = m & 2047;
            int n = nOff + cc, h = n >> 6, dd = n & 63;
            size_t base = ((size_t)(b * HH + h) * SS + s) * AK2;
            uint32_t hp[4], lp[4];
#pragma unroll
            for (int j2 = 0; j2 < 4; j2++) {
                float v0 = (ep[r * 129 + cc + 2 * j2] + bi[n + 2 * j2]) * sc;
                float v1 = (ep[r * 129 + cc + 2 * j2 + 1] + bi[n + 2 * j2 + 1]) * sc;
                hp[j2] = packhi(v0, v1);
                lp[j2] = packlo2(lopart(v0), lopart(v1));
            }
            *(uint4*)&out[base + dd] = *(uint4*)&hp[0];
            *(uint4*)&out[base + 64 + dd] = *(uint4*)&lp[0];
        }
    }
}

// ---------------------------------------------------------------------------
// Kernel 3: HMMA flash attention v5. CTA = (b,h) x 128 q; 4 warps x 32q
// (two 16-row a-groups per warp share every K/V b-fragment). 128 threads,
// 2 CTAs/SM. Base-2 softmax (log2e folded into Q). Register-resident split P.
// ---------------------------------------------------------------------------
#define APITCH 272
#define AQSZ (128 * APITCH)          // 34816
#define AKVT (64 * APITCH)           // 17408 per K (or V) tile
#define ASTG (2 * AKVT)              // 34816 per stage
#define ATTN_SMEM (AQSZ + 2 * ASTG)  // 104448
#define ATHR 128

__device__ __forceinline__ void load_kv(uint32_t sb, int tid,
                                        const __nv_bfloat16* Kg,
                                        const __nv_bfloat16* Vg, int kt, int st) {
#pragma unroll
    for (int i = 0; i < 16; i++) {
        int idx = tid + i * ATHR;          // 0..2047
        int t = idx >= 1024;               // 0 = K, 1 = V
        int j = idx - t * 1024;
        int r = j >> 4, seg = j & 15;      // 16 segs of 16B = 256B/row
        uint32_t so = AQSZ + st * ASTG + t * AKVT + r * APITCH + seg * 16;
        size_t go = ((size_t)kt * 64 + r) * AK2 + seg * 8;
        cp16(sb + so, (t ? Vg : Kg) + go);
    }
    CP_COMMIT();
}

__global__ __launch_bounds__(ATHR)
void attn_hmma(const __nv_bfloat16* __restrict__ Qs,
               const __nv_bfloat16* __restrict__ Ks,
               const __nv_bfloat16* __restrict__ Vt,
               __nv_bfloat16* __restrict__ O) {
    extern __shared__ char smem[];
    const uint32_t sb = smem_u32(smem);
    const int tid = threadIdx.x, w = tid >> 5, lane = tid & 31;
    const int bh = blockIdx.y;
    const int q0 = blockIdx.x * 128;
    const __nv_bfloat16* Qg = Qs + ((size_t)bh * SS + q0) * AK2;
    const __nv_bfloat16* Kg = Ks + (size_t)bh * SS * AK2;
    const __nv_bfloat16* Vg = Vt + (size_t)bh * (32 * 64 * AK2);

#pragma unroll
    for (int i = 0; i < 16; i++) {
        int idx = tid + i * ATHR;
        int row = idx >> 4, seg = idx & 15;
        cp16(sb + row * APITCH + seg * 16, Qg + (size_t)row * AK2 + seg * 8);
    }
    load_kv(sb, tid, Kg, Vg, 0, 0);
    load_kv(sb, tid, Kg, Vg, 1, 1);

    float o[2][8][4];
    float mi[2][2], li[2][2];
#pragma unroll
    for (int g = 0; g < 2; g++) {
        mi[g][0] = mi[g][1] = -1e30f;
        li[g][0] = li[g][1] = 0.f;
#pragma unroll
        for (int nj = 0; nj < 8; nj++)
#pragma unroll
            for (int r = 0; r < 4; r++) o[g][nj][r] = 0.f;
    }

    const uint32_t aQ = sb + (w * 32 + (lane & 15)) * APITCH + (lane >> 4) * 16;
    const uint32_t bKb = sb + AQSZ + (lane & 15) * APITCH + (lane >> 4) * 16;

    for (int kt = 0; kt < 32; kt++) {
        if (kt == 31) CP_WAIT0(); else CP_WAIT1();
        __syncthreads();
        const uint32_t stoff = (kt & 1) * ASTG;

        // --- S = qh·kh + ql·kh + qh·kl  (b-frags shared by both a-groups) ---
        float sc[2][8][4];
#pragma unroll
        for (int g = 0; g < 2; g++)
#pragma unroll
            for (int nj = 0; nj < 8; nj++)
#pragma unroll
                for (int r = 0; r < 4; r++) sc[g][nj][r] = 0.f;
#pragma unroll
        for (int ks = 0; ks < 4; ks++) {
            uint32_t bkh[4][4], bkl[4][4];
#pragma unroll
            for (int j2 = 0; j2 < 4; j2++) {
                ldsm4(bkh[j2], bKb + stoff + j2 * 16 * APITCH + ks * 32);
                ldsm4(bkl[j2], bKb + stoff + 128 + j2 * 16 * APITCH + ks * 32);
            }
#pragma unroll
            for (int g = 0; g < 2; g++) {
                uint32_t aqh[4], aql[4];
                ldsm4(aqh, aQ + g * 16 * APITCH + ks * 32);
                ldsm4(aql, aQ + g * 16 * APITCH + 128 + ks * 32);
#pragma unroll
                for (int nj = 0; nj < 8; nj++) {
                    uint32_t b0 = bkh[nj >> 1][nj & 1], b1 = bkh[nj >> 1][(nj & 1) + 2];
                    mma16816(sc[g][nj], aqh, b0, b1);
                    mma16816(sc[g][nj], aql, b0, b1);
                    mma16816(sc[g][nj], aqh,
                             bkl[nj >> 1][nj & 1], bkl[nj >> 1][(nj & 1) + 2]);
                }
            }
        }

        // --- base-2 online softmax; cheap-split P -> register A-fragments ---
        uint32_t aPhi[2][4][4], aPlo[2][4][4];
#pragma unroll
        for (int g = 0; g < 2; g++)
#pragma unroll
            for (int rr = 0; rr < 2; rr++) {
                float mx = -1e30f;
#pragma unroll
                for (int nj = 0; nj < 8; nj++)
                    mx = fmaxf(mx, fmaxf(sc[g][nj][rr * 2], sc[g][nj][rr * 2 + 1]));
                mx = fmaxf(mx, __shfl_xor_sync(0xffffffffu, mx, 1));
                mx = fmaxf(mx, __shfl_xor_sync(0xffffffffu, mx, 2));
                float mn = fmaxf(mi[g][rr], mx);
                float rs = 0.f;
#pragma unroll
                for (int nj = 0; nj < 8; nj++) {
                    float p0 = ex2(sc[g][nj][rr * 2] - mn);
                    float p1 = ex2(sc[g][nj][rr * 2 + 1] - mn);
                    rs += p0 + p1;
                    aPhi[g][nj >> 1][(nj & 1) * 2 + rr] = packhi(p0, p1);
                    aPlo[g][nj >> 1][(nj & 1) * 2 + rr] = packlo2(lopart(p0), lopart(p1));
                }
                rs += __shfl_xor_sync(0xffffffffu, rs, 1);
                rs += __shfl_xor_sync(0xffffffffu, rs, 2);
                float f = ex2(mi[g][rr] - mn);
                li[g][rr] = li[g][rr] * f + rs;
                mi[g][rr] = mn;
#pragma unroll
                for (int nj = 0; nj < 8; nj++) {
                    o[g][nj][rr * 2] *= f;
                    o[g][nj][rr * 2 + 1] *= f;
                }
            }

        // --- O += Phi·vh + Plo·vh + Phi·vl  (b-frags shared by groups) ---
        const uint32_t bVb = bKb + AKVT + stoff;
#pragma unroll
        for (int kk = 0; kk < 4; kk++) {
            uint32_t bvh[4][4], bvl[4][4];
#pragma unroll
            for (int j2 = 0; j2 < 4; j2++) {
                ldsm4(bvh[j2], bVb + j2 * 16 * APITCH + kk * 32);
                ldsm4(bvl[j2], bVb + 128 + j2 * 16 * APITCH + kk * 32);
            }
#pragma unroll
            for (int g = 0; g < 2; g++)
#pragma unroll
                for (int nj = 0; nj < 8; nj++) {
                    uint32_t b0 = bvh[nj >> 1][nj & 1], b1 = bvh[nj >> 1][(nj & 1) + 2];
                    mma16816(o[g][nj], aPhi[g][kk], b0, b1);
                    mma16816(o[g][nj], aPlo[g][kk], b0, b1);
                    mma16816(o[g][nj], aPhi[g][kk],
                             bvl[nj >> 1][nj & 1], bvl[nj >> 1][(nj & 1) + 2]);
                }
        }
        __syncthreads();
        if (kt + 2 < 32) load_kv(sb, tid, Kg, Vg, kt + 2, kt & 1);
    }

    // --- epilogue: normalize, emit [oh|ol] rows for Wo GEMM ---
    const int b_ = bh >> 4, h_ = bh & 15;
    const int q4 = lane & 3;
#pragma unroll
    for (int g = 0; g < 2; g++)
#pragma unroll
        for (int rr = 0; rr < 2; rr++) {
            float inv = 1.f / li[g][rr];
            size_t base = ((size_t)b_ * SS + q0 + w * 32 + g * 16 + rr * 8 + (lane >> 2))
                          * (size_t)K2;
#pragma unroll
            for (int nj = 0; nj < 8; nj++) {
                int d = nj * 8 + 2 * q4;
                float v0 = o[g][nj][rr * 2] * inv, v1 = o[g][nj][rr * 2 + 1] * inv;
                *(uint32_t*)&O[base + h_ * 64 + d] = packhi(v0, v1);
                *(uint32_t*)&O[base + 1024 + h_ * 64 + d] = packlo2(lopart(v0), lopart(v1));
            }
        }
}

// ---------------------------------------------------------------------------
extern "C" void kernel_launch(void* const* d_in, const int* in_sizes, int n_in,
                              void* d_out, int out_size) {
    const float* x  = (const float*)d_in[0];
    const float* Wq = (const float*)d_in[1];
    const float* bq = (const float*)d_in[2];
    const float* Wk = (const float*)d_in[3];
    const float* bk = (const float*)d_in[4];
    const float* Wv = (const float*)d_in[5];
    const float* bv = (const float*)d_in[6];
    const float* Wo = (const float*)d_in[7];
    const float* bo = (const float*)d_in[8];

    __nv_bfloat16 *xTb, *wqkv, *wob, *qs, *ks, *vt, *attb;
    cudaGetSymbolAddress((void**)&xTb, g_xTbig);
    cudaGetSymbolAddress((void**)&wqkv, g_Wqkv);
    cudaGetSymbolAddress((void**)&wob, g_Wob);
    cudaGetSymbolAddress((void**)&qs, g_Qs);
    cudaGetSymbolAddress((void**)&ks, g_Ks);
    cudaGetSymbolAddress((void**)&vt, g_Vt);
    cudaGetSymbolAddress((void**)&attb, g_attbig);

    pe_transpose_split<<<dim3(SS / 32, DM / 32, BB), dim3(32, 32)>>>(x, xTb);
    wsplit_kernel<<<dim3(DM * DM / 256, 4), 256>>>(Wq, Wk, Wv, Wo, wqkv, wob);

    cudaFuncSetAttribute(hmma_gemm<0>, cudaFuncAttributeMaxDynamicSharedMemorySize, GEMM_SMEM);
    cudaFuncSetAttribute(hmma_gemm<3>, cudaFuncAttributeMaxDynamicSharedMemorySize, GEMM_SMEM);
    dim3 ggQKV(3 * DM / 128, (BB * SS) / 128);  // (24, 64)
    dim3 gg(DM / 128, (BB * SS) / 128);         // (8, 64)
    hmma_gemm<0><<<ggQKV, 256, GEMM_SMEM>>>(xTb, wqkv, bq, bk, bv, qs, ks, vt);

    cudaFuncSetAttribute(attn_hmma, cudaFuncAttributeMaxDynamicSharedMemorySize, ATTN_SMEM);
    attn_hmma<<<dim3(SS / 128, BB * HH), ATHR, ATTN_SMEM>>>(qs, ks, vt, attb);

    hmma_gemm<3><<<gg, 256, GEMM_SMEM>>>(attb, wob, bo, nullptr, nullptr,
                                         d_out, nullptr, nullptr);
}

// round 14
// speedup vs baseline: 1.1338x; 1.1338x over previous
#include <cuda_runtime.h>
#include <cuda_bf16.h>
#include <cuda_fp16.h>
#include <math.h>
#include <stdint.h>

#define BB 4
#define DM 1024
#define SS 2048
#define HH 16
#define HD 64
#define K2 2048   // GEMM rows: [hi x1024 | lo x1024] (bf16 split, projections)
#define QW 64     // Q rows: 64 fp16
#define KW 128    // K/V rows: [hi64|lo64] fp16

// ---------------- scratch (device globals; allocation-free) ----------------
__device__ __nv_bfloat16 g_xTbig[(size_t)BB * SS * K2];
__device__ __nv_bfloat16 g_Wqkv[(size_t)3 * DM * K2];  // [Wq ; Wk ; Wv] split rows
__device__ __nv_bfloat16 g_Wob[(size_t)DM * K2];
__device__ __half g_Qs[(size_t)BB * HH * SS * QW];     // fp16, x(log2e/8)
__device__ __half g_Ks[(size_t)BB * HH * SS * KW];     // [kh|kl] fp16
__device__ __half g_Vt[(size_t)BB * HH * 32 * HD * KW]; // V^T [vh|vl] fp16
__device__ __nv_bfloat16 g_attbig[(size_t)BB * SS * K2];

// ---------------- helpers ----------------
__device__ __forceinline__ uint32_t smem_u32(const void* p) {
    uint32_t a;
    asm("{ .reg .u64 t; cvta.to.shared.u64 t, %1; cvt.u32.u64 %0, t; }" : "=r"(a) : "l"(p));
    return a;
}
__device__ __forceinline__ void cp16(uint32_t s, const void* g) {
    asm volatile("cp.async.cg.shared.global [%0], [%1], 16;" :: "r"(s), "l"(g) : "memory");
}
#define CP_COMMIT() asm volatile("cp.async.commit_group;" ::: "memory")
#define CP_WAIT1()  asm volatile("cp.async.wait_group 1;" ::: "memory")
#define CP_WAIT0()  asm volatile("cp.async.wait_group 0;" ::: "memory")

__device__ __forceinline__ void ldsm4(uint32_t* r, uint32_t addr) {
    asm volatile("ldmatrix.sync.aligned.m8n8.x4.shared.b16 {%0,%1,%2,%3}, [%4];"
                 : "=r"(r[0]), "=r"(r[1]), "=r"(r[2]), "=r"(r[3]) : "r"(addr));
}
__device__ __forceinline__ void mma16816(float* c, const uint32_t* a,
                                         uint32_t b0, uint32_t b1) {
    asm volatile("mma.sync.aligned.m16n8k16.row.col.f32.bf16.bf16.f32 "
                 "{%0,%1,%2,%3}, {%4,%5,%6,%7}, {%8,%9}, {%0,%1,%2,%3};"
                 : "+f"(c[0]), "+f"(c[1]), "+f"(c[2]), "+f"(c[3])
                 : "r"(a[0]), "r"(a[1]), "r"(a[2]), "r"(a[3]), "r"(b0), "r"(b1));
}
__device__ __forceinline__ void mma16816h(float* c, const uint32_t* a,
                                          uint32_t b0, uint32_t b1) {
    asm volatile("mma.sync.aligned.m16n8k16.row.col.f32.f16.f16.f32 "
                 "{%0,%1,%2,%3}, {%4,%5,%6,%7}, {%8,%9}, {%0,%1,%2,%3};"
                 : "+f"(c[0]), "+f"(c[1]), "+f"(c[2]), "+f"(c[3])
                 : "r"(a[0]), "r"(a[1]), "r"(a[2]), "r"(a[3]), "r"(b0), "r"(b1));
}
__device__ __forceinline__ float ex2(float x) {
    float y;
    asm("ex2.approx.f32 %0, %1;" : "=f"(y) : "f"(x));
    return y;
}
// bf16 round split (prep kernels + bf16 epilogues)
__device__ __forceinline__ void split2(float v, __nv_bfloat16& hi, __nv_bfloat16& lo) {
    hi = __float2bfloat16(v);
    lo = __float2bfloat16(v - __bfloat162float(hi));
}
__device__ __forceinline__ uint32_t packhi(float a, float b) {
    return __byte_perm(__float_as_uint(a), __float_as_uint(b), 0x7632);
}
__device__ __forceinline__ float lopart(float v) {
    return v - __uint_as_float(__float_as_uint(v) & 0xFFFF0000u);
}
__device__ __forceinline__ uint32_t packlo2(float l0, float l1) {
    uint32_t r;
    asm("cvt.rn.bf16x2.f32 %0, %1, %2;" : "=r"(r) : "f"(l1), "f"(l0));
    return r;  // l0 in low half
}
// fp16 pack (a in low half)
__device__ __forceinline__ uint32_t pack2h(float a, float b) {
    uint32_t r;
    asm("cvt.rn.f16x2.f32 %0, %1, %2;" : "=r"(r) : "f"(b), "f"(a));
    return r;
}
// fp16 round split
__device__ __forceinline__ void split2h(float v, __half& hi, __half& lo) {
    hi = __float2half_rn(v);
    lo = __float2half_rn(v - __half2float(hi));
}

// ---------------------------------------------------------------------------
// Kernel 1: x[B,D,S] + PE -> xTbig rows [ah | al]
// ---------------------------------------------------------------------------
__global__ void pe_transpose_split(const float* __restrict__ x,
                                   __nv_bfloat16* __restrict__ out) {
    __shared__ float tile[32][33];
    int b = blockIdx.z;
    int d0 = blockIdx.y * 32, s0 = blockIdx.x * 32;
    int d = d0 + threadIdx.y, s = s0 + threadIdx.x;
    float denom = expf((float)(d & ~1) * (-9.210340371976184f / (float)DM));
    float ang = (float)s * denom;
    float pe = (d & 1) ? cosf(ang) : sinf(ang);
    tile[threadIdx.y][threadIdx.x] = x[((size_t)b * DM + d) * SS + s] + pe;
    __syncthreads();
    int s2 = s0 + threadIdx.y, d2 = d0 + threadIdx.x;
    float v = tile[threadIdx.x][threadIdx.y];
    __nv_bfloat16 hi, lo; split2(v, hi, lo);
    size_t base = ((size_t)b * SS + s2) * K2;
    out[base + d2] = hi;
    out[base + 1024 + d2] = lo;
}

// ---------------------------------------------------------------------------
// Kernel 1b: weight split -> rows [wh | wl]; Wq,Wk,Wv into one buffer
// ---------------------------------------------------------------------------
__global__ void wsplit_kernel(const float* __restrict__ w0, const float* __restrict__ w1,
                              const float* __restrict__ w2, const float* __restrict__ w3,
                              __nv_bfloat16* oqkv, __nv_bfloat16* oo) {
    const float* src; __nv_bfloat16* dst;
    switch (blockIdx.y) {
        case 0: src = w0; dst = oqkv; break;
        case 1: src = w1; dst = oqkv + (size_t)DM * K2; break;
        case 2: src = w2; dst = oqkv + (size_t)2 * DM * K2; break;
        default: src = w3; dst = oo; break;
    }
    int idx = blockIdx.x * 256 + threadIdx.x;
    int n = idx >> 10, dcol = idx & 1023;
    __nv_bfloat16 hi, lo; split2(src[idx], hi, lo);
    size_t base = (size_t)n * K2;
    dst[base + dcol] = hi;
    dst[base + 1024 + dcol] = lo;
}

// ---------------------------------------------------------------------------
// Kernel 2: HMMA GEMM (bf16 3-pass mainloop; MODE 0 fused QKV, MODE 3 final)
// QKV epilogues now emit fp16 attention layouts.
// ---------------------------------------------------------------------------
#define STG 40960
#define GEMM_SMEM 81920
#define QSCALE 0.18033688011112042f  // 0.125 * log2(e)

template <int MODE>
__global__ __launch_bounds__(256, 2)
void hmma_gemm(const __nv_bfloat16* __restrict__ A, const __nv_bfloat16* __restrict__ W,
               const float* __restrict__ bias, const float* __restrict__ bias2,
               const float* __restrict__ bias3,
               void* __restrict__ outv, void* __restrict__ outv2,
               void* __restrict__ outv3) {
    extern __shared__ char smem[];
    const uint32_t sb = smem_u32(smem);
    const int tid = threadIdx.x, wid = tid >> 5, lane = tid & 31;
    const int wr = wid >> 1, wc = wid & 1;
    const int mBase = blockIdx.y * 128, nBase = blockIdx.x * 128;

    float acc[2][8][4];
#pragma unroll
    for (int i = 0; i < 2; i++)
#pragma unroll
        for (int j = 0; j < 8; j++)
#pragma unroll
            for (int r = 0; r < 4; r++) acc[i][j][r] = 0.f;

    const int r0 = tid >> 2, c4 = tid & 3;
    const __nv_bfloat16* gA = A + (size_t)(mBase + r0) * K2 + c4 * 8;
    const __nv_bfloat16* gW = W + (size_t)(nBase + r0) * K2 + c4 * 8;

#define LOAD_CHUNK(c, st)                                                     \
    do {                                                                      \
        uint32_t s0 = sb + (st) * STG + r0 * 80 + c4 * 16;                    \
        cp16(s0,                 gA + (c) * 32);                              \
        cp16(s0 + 64 * 80,       gA + (size_t)64 * K2 + (c) * 32);            \
        cp16(s0 + 10240,         gA + 1024 + (c) * 32);                       \
        cp16(s0 + 10240 + 64*80, gA + (size_t)64 * K2 + 1024 + (c) * 32);     \
        cp16(s0 + 20480,         gW + (c) * 32);                              \
        cp16(s0 + 20480 + 64*80, gW + (size_t)64 * K2 + (c) * 32);            \
        cp16(s0 + 30720,         gW + 1024 + (c) * 32);                       \
        cp16(s0 + 30720 + 64*80, gW + (size_t)64 * K2 + 1024 + (c) * 32);     \
        CP_COMMIT();                                                          \
    } while (0)

    LOAD_CHUNK(0, 0);
    LOAD_CHUNK(1, 1);

    const uint32_t aB = (wr * 32 + (lane & 15)) * 80 + (lane >> 4) * 16;
    const uint32_t bB = 20480 + (wc * 64 + (lane & 15)) * 80 + (lane >> 4) * 16;

    const int NCH = 1024 / 32;  // 32
    for (int c = 0; c < NCH; c++) {
        if (c == NCH - 1) CP_WAIT0(); else CP_WAIT1();
        __syncthreads();
        const uint32_t stg = sb + (c & 1) * STG;
#pragma unroll
        for (int ks = 0; ks < 2; ks++) {
            uint32_t ah[2][4], al[2][4], bh[4][4], bl[4][4];
            ldsm4(ah[0], stg + aB + ks * 32);
            ldsm4(ah[1], stg + aB + 16 * 80 + ks * 32);
            ldsm4(al[0], stg + aB + 10240 + ks * 32);
            ldsm4(al[1], stg + aB + 10240 + 16 * 80 + ks * 32);
#pragma unroll
            for (int j2 = 0; j2 < 4; j2++) {
                ldsm4(bh[j2], stg + bB + j2 * 16 * 80 + ks * 32);
                ldsm4(bl[j2], stg + bB + 10240 + j2 * 16 * 80 + ks * 32);
            }
#pragma unroll
            for (int mi = 0; mi < 2; mi++)
#pragma unroll
                for (int nj = 0; nj < 8; nj++) {
                    uint32_t b0 = bh[nj >> 1][nj & 1], b1 = bh[nj >> 1][(nj & 1) + 2];
                    mma16816(acc[mi][nj], ah[mi], b0, b1);
                    mma16816(acc[mi][nj], al[mi], b0, b1);
                    mma16816(acc[mi][nj], ah[mi],
                             bl[nj >> 1][nj & 1], bl[nj >> 1][(nj & 1) + 2]);
                }
        }
        __syncthreads();
        if (c + 2 < NCH) LOAD_CHUNK(c + 2, c & 1);
    }
#undef LOAD_CHUNK

    __syncthreads();
    float* ep = (float*)smem;
#pragma unroll
    for (int mi = 0; mi < 2; mi++)
#pragma unroll
        for (int nj = 0; nj < 8; nj++) {
            int row = wr * 32 + mi * 16 + (lane >> 2);
            int col = wc * 64 + nj * 8 + (lane & 3) * 2;
            ep[row * 129 + col] = acc[mi][nj][0];
            ep[row * 129 + col + 1] = acc[mi][nj][1];
            ep[(row + 8) * 129 + col] = acc[mi][nj][2];
            ep[(row + 8) * 129 + col + 1] = acc[mi][nj][3];
        }
    __syncthreads();

    if (MODE == 3) {
        float* out = (float*)outv;
        int nl = tid >> 1;
        int n = nBase + nl;
        float bn = bias[n];
#pragma unroll
        for (int ii = 0; ii < 16; ii++) {
            int sl = (tid & 1) * 64 + ii * 4;
            int m0 = mBase + sl, b = m0 >> 11, s = m0 & 2047;
            float4 v;
            v.x = ep[(sl + 0) * 129 + nl] + bn;
            v.y = ep[(sl + 1) * 129 + nl] + bn;
            v.z = ep[(sl + 2) * 129 + nl] + bn;
            v.w = ep[(sl + 3) * 129 + nl] + bn;
            *(float4*)&out[((size_t)b * DM + n) * SS + s] = v;
        }
    } else if (nBase >= 2048) {
        // V^T: [bh, chunk, d, [vh64|vl64]] fp16; coalesced uint4 stores.
        __half* out = (__half*)outv3;
        int b = mBase >> 11, s0 = mBase & 2047;
#pragma unroll
        for (int it = 0; it < 8; it++) {
            int t = tid + it * 256;
            int dl = t >> 4;
            int rem = t & 15;
            int ch = rem >> 3, jb = (rem & 7) * 8;
            int n = nBase - 2048 + dl;
            int h = n >> 6, dd = n & 63;
            float bn = bias3[n];
            size_t vb = (((size_t)(b * HH + h)) * 32 + (s0 >> 6) + ch) * (64 * KW)
                        + (size_t)dd * KW;
            uint32_t hp[4], lp[4];
#pragma unroll
            for (int j2 = 0; j2 < 4; j2++) {
                float v0 = ep[(ch * 64 + jb + 2 * j2) * 129 + dl] + bn;
                float v1 = ep[(ch * 64 + jb + 2 * j2 + 1) * 129 + dl] + bn;
                __half h0, l0, h1, l1;
                split2h(v0, h0, l0); split2h(v1, h1, l1);
                hp[j2] = (uint32_t)__half_as_ushort(h0) |
                         ((uint32_t)__half_as_ushort(h1) << 16);
                lp[j2] = (uint32_t)__half_as_ushort(l0) |
                         ((uint32_t)__half_as_ushort(l1) << 16);
            }
            *(uint4*)&out[vb + jb] = *(uint4*)&hp[0];
            *(uint4*)&out[vb + 64 + jb] = *(uint4*)&lp[0];
        }
    } else if (nBase >= 1024) {
        // K: rows [kh64|kl64] fp16
        __half* out = (__half*)outv2;
#pragma unroll
        for (int i = 0; i < 8; i++) {
            int r = (tid >> 4) + i * 16;
            int cc = (tid & 15) * 8;
            int m = mBase + r, b = m >> 11, s = m & 2047;
            int n = nBase - 1024 + cc, h = n >> 6, dd = n & 63;
            size_t base = ((size_t)(b * HH + h) * SS + s) * KW;
            uint32_t hp[4], lp[4];
#pragma unroll
            for (int j2 = 0; j2 < 4; j2++) {
                float v0 = ep[r * 129 + cc + 2 * j2] + bias2[n + 2 * j2];
                float v1 = ep[r * 129 + cc + 2 * j2 + 1] + bias2[n + 2 * j2 + 1];
                __half h0, l0, h1, l1;
                split2h(v0, h0, l0); split2h(v1, h1, l1);
                hp[j2] = (uint32_t)__half_as_ushort(h0) |
                         ((uint32_t)__half_as_ushort(h1) << 16);
                lp[j2] = (uint32_t)__half_as_ushort(l0) |
                         ((uint32_t)__half_as_ushort(l1) << 16);
            }
            *(uint4*)&out[base + dd] = *(uint4*)&hp[0];
            *(uint4*)&out[base + 64 + dd] = *(uint4*)&lp[0];
        }
    } else {
        // Q: rows of 64 fp16, xQSCALE
        __half* out = (__half*)outv;
#pragma unroll
        for (int i = 0; i < 8; i++) {
            int r = (tid >> 4) + i * 16;
            int cc = (tid & 15) * 8;
            int m = mBase + r, b = m >> 11, s = m & 2047;
            int n = nBase + cc, h = n >> 6, dd = n & 63;
            size_t base = ((size_t)(b * HH + h) * SS + s) * QW;
            uint32_t qp[4];
#pragma unroll
            for (int j2 = 0; j2 < 4; j2++) {
                float v0 = (ep[r * 129 + cc + 2 * j2] + bias[n + 2 * j2]) * QSCALE;
                float v1 = (ep[r * 129 + cc + 2 * j2 + 1] + bias[n + 2 * j2 + 1]) * QSCALE;
                qp[j2] = pack2h(v0, v1);
            }
            *(uint4*)&out[base + dd] = *(uint4*)&qp[0];
        }
    }
}

// ---------------------------------------------------------------------------
// Kernel 3: fp16 HMMA flash attention. CTA = (b,h) x 128 q; 8 warps x 16q;
// 2-stage KV ring; base-2 softmax; P single fp16; 4 MMA passes/iter.
// ---------------------------------------------------------------------------
#define QPITCH 144
#define AQSZ (128 * QPITCH)          // 18432
#define KVPITCH 272
#define AKVT (64 * KVPITCH)          // 17408 per K (or V) tile
#define ASTG (2 * AKVT)              // 34816 per stage
#define ATTN_SMEM (AQSZ + 2 * ASTG)  // 88064

__device__ __forceinline__ void load_kv(uint32_t sb, int tid,
                                        const __half* Kg, const __half* Vg,
                                        int kt, int st) {
#pragma unroll
    for (int i = 0; i < 8; i++) {
        int idx = tid + i * 256;           // 0..2047
        int t = idx >= 1024;               // 0 = K, 1 = V
        int j = idx - t * 1024;
        int r = j >> 4, seg = j & 15;      // 16 segs of 16B = 256B/row
        uint32_t so = AQSZ + st * ASTG + t * AKVT + r * KVPITCH + seg * 16;
        size_t go = ((size_t)kt * 64 + r) * KW + seg * 8;
        cp16(sb + so, (t ? Vg : Kg) + go);
    }
    CP_COMMIT();
}

__global__ __launch_bounds__(256, 2)
void attn_hmma(const __half* __restrict__ Qs, const __half* __restrict__ Ks,
               const __half* __restrict__ Vt, __nv_bfloat16* __restrict__ O) {
    extern __shared__ char smem[];
    const uint32_t sb = smem_u32(smem);
    const int tid = threadIdx.x, w = tid >> 5, lane = tid & 31;
    const int bh = blockIdx.y;
    const int q0 = blockIdx.x * 128;
    const __half* Qg = Qs + ((size_t)bh * SS + q0) * QW;
    const __half* Kg = Ks + (size_t)bh * SS * KW;
    const __half* Vg = Vt + (size_t)bh * (32 * 64 * KW);

    // prologue: Q (128 rows x 128B) joins group0 with KV0; then KV1
#pragma unroll
    for (int i = 0; i < 4; i++) {
        int idx = tid + i * 256;           // 0..1023
        int row = idx >> 3, seg = idx & 7;
        cp16(sb + row * QPITCH + seg * 16, Qg + (size_t)row * QW + seg * 8);
    }
    load_kv(sb, tid, Kg, Vg, 0, 0);
    load_kv(sb, tid, Kg, Vg, 1, 1);

    float o[8][4];
    float mi[2] = {-1e30f, -1e30f}, li[2] = {0.f, 0.f};
#pragma unroll
    for (int nj = 0; nj < 8; nj++)
#pragma unroll
        for (int r = 0; r < 4; r++) o[nj][r] = 0.f;

    const int q4 = lane & 3;
    const int r1 = w * 16 + (lane >> 2);
    const uint32_t aQ = sb + (w * 16 + (lane & 15)) * QPITCH + (lane >> 4) * 16;
    const uint32_t bKb = sb + AQSZ + (lane & 15) * KVPITCH + (lane >> 4) * 16;

    for (int kt = 0; kt < 32; kt++) {
        if (kt == 31) CP_WAIT0(); else CP_WAIT1();
        __syncthreads();
        const uint32_t stoff = (kt & 1) * ASTG;

        // --- S = qf·kh + qf·kl ---
        float sc[8][4];
#pragma unroll
        for (int nj = 0; nj < 8; nj++)
#pragma unroll
            for (int r = 0; r < 4; r++) sc[nj][r] = 0.f;
#pragma unroll
        for (int ks = 0; ks < 4; ks++) {
            uint32_t aq[4], bkh[4][4], bkl[4][4];
            ldsm4(aq, aQ + ks * 32);
#pragma unroll
            for (int j2 = 0; j2 < 4; j2++) {
                ldsm4(bkh[j2], bKb + stoff + j2 * 16 * KVPITCH + ks * 32);
                ldsm4(bkl[j2], bKb + stoff + 128 + j2 * 16 * KVPITCH + ks * 32);
            }
#pragma unroll
            for (int nj = 0; nj < 8; nj++) {
                mma16816h(sc[nj], aq, bkh[nj >> 1][nj & 1], bkh[nj >> 1][(nj & 1) + 2]);
                mma16816h(sc[nj], aq, bkl[nj >> 1][nj & 1], bkl[nj >> 1][(nj & 1) + 2]);
            }
        }

        // --- base-2 online softmax; P -> single fp16 register A-fragments ---
        uint32_t aPf[4][4];
#pragma unroll
        for (int rr = 0; rr < 2; rr++) {
            float mx = -1e30f;
#pragma unroll
            for (int nj = 0; nj < 8; nj++)
                mx = fmaxf(mx, fmaxf(sc[nj][rr * 2], sc[nj][rr * 2 + 1]));
            mx = fmaxf(mx, __shfl_xor_sync(0xffffffffu, mx, 1));
            mx = fmaxf(mx, __shfl_xor_sync(0xffffffffu, mx, 2));
            float mn = fmaxf(mi[rr], mx);
            float rs = 0.f;
#pragma unroll
            for (int nj = 0; nj < 8; nj++) {
                float p0 = ex2(sc[nj][rr * 2] - mn);
                float p1 = ex2(sc[nj][rr * 2 + 1] - mn);
                rs += p0 + p1;
                aPf[nj >> 1][(nj & 1) * 2 + rr] = pack2h(p0, p1);
            }
            rs += __shfl_xor_sync(0xffffffffu, rs, 1);
            rs += __shfl_xor_sync(0xffffffffu, rs, 2);
            float f = ex2(mi[rr] - mn);
            li[rr] = li[rr] * f + rs;
            mi[rr] = mn;
#pragma unroll
            for (int nj = 0; nj < 8; nj++) {
                o[nj][rr * 2] *= f;
                o[nj][rr * 2 + 1] *= f;
            }
        }

        // --- O += Pf·vh + Pf·vl ---
        const uint32_t bVb = bKb + AKVT + stoff;
#pragma unroll
        for (int kk = 0; kk < 4; kk++) {
            uint32_t bvh[4][4], bvl[4][4];
#pragma unroll
            for (int j2 = 0; j2 < 4; j2++) {
                ldsm4(bvh[j2], bVb + j2 * 16 * KVPITCH + kk * 32);
                ldsm4(bvl[j2], bVb + 128 + j2 * 16 * KVPITCH + kk * 32);
            }
#pragma unroll
            for (int nj = 0; nj < 8; nj++) {
                mma16816h(o[nj], aPf[kk], bvh[nj >> 1][nj & 1], bvh[nj >> 1][(nj & 1) + 2]);
                mma16816h(o[nj], aPf[kk], bvl[nj >> 1][nj & 1], bvl[nj >> 1][(nj & 1) + 2]);
            }
        }
        __syncthreads();
        if (kt + 2 < 32) load_kv(sb, tid, Kg, Vg, kt + 2, kt & 1);
    }

    // --- epilogue: normalize, emit bf16 [oh|ol] rows for Wo GEMM ---
    const int b_ = bh >> 4, h_ = bh & 15;
#pragma unroll
    for (int rr = 0; rr < 2; rr++) {
        float inv = 1.f / li[rr];
        size_t base = ((size_t)b_ * SS + q0 + r1 + rr * 8) * (size_t)K2;
#pragma unroll
        for (int nj = 0; nj < 8; nj++) {
            int d = nj * 8 + 2 * q4;
            float v0 = o[nj][rr * 2] * inv, v1 = o[nj][rr * 2 + 1] * inv;
            *(uint32_t*)&O[base + h_ * 64 + d] = packhi(v0, v1);
            *(uint32_t*)&O[base + 1024 + h_ * 64 + d] = packlo2(lopart(v0), lopart(v1));
        }
    }
}

// ---------------------------------------------------------------------------
extern "C" void kernel_launch(void* const* d_in, const int* in_sizes, int n_in,
                              void* d_out, int out_size) {
    const float* x  = (const float*)d_in[0];
    const float* Wq = (const float*)d_in[1];
    const float* bq = (const float*)d_in[2];
    const float* Wk = (const float*)d_in[3];
    const float* bk = (const float*)d_in[4];
    const float* Wv = (const float*)d_in[5];
    const float* bv = (const float*)d_in[6];
    const float* Wo = (const float*)d_in[7];
    const float* bo = (const float*)d_in[8];

    __nv_bfloat16 *xTb, *wqkv, *wob, *attb;
    __half *qs, *ks, *vt;
    cudaGetSymbolAddress((void**)&xTb, g_xTbig);
    cudaGetSymbolAddress((void**)&wqkv, g_Wqkv);
    cudaGetSymbolAddress((void**)&wob, g_Wob);
    cudaGetSymbolAddress((void**)&qs, g_Qs);
    cudaGetSymbolAddress((void**)&ks, g_Ks);
    cudaGetSymbolAddress((void**)&vt, g_Vt);
    cudaGetSymbolAddress((void**)&attb, g_attbig);

    pe_transpose_split<<<dim3(SS / 32, DM / 32, BB), dim3(32, 32)>>>(x, xTb);
    wsplit_kernel<<<dim3(DM * DM / 256, 4), 256>>>(Wq, Wk, Wv, Wo, wqkv, wob);

    cudaFuncSetAttribute(hmma_gemm<0>, cudaFuncAttributeMaxDynamicSharedMemorySize, GEMM_SMEM);
    cudaFuncSetAttribute(hmma_gemm<3>, cudaFuncAttributeMaxDynamicSharedMemorySize, GEMM_SMEM);
    dim3 ggQKV(3 * DM / 128, (BB * SS) / 128);  // (24, 64)
    dim3 gg(DM / 128, (BB * SS) / 128);         // (8, 64)
    hmma_gemm<0><<<ggQKV, 256, GEMM_SMEM>>>(xTb, wqkv, bq, bk, bv, qs, ks, vt);

    cudaFuncSetAttribute(attn_hmma, cudaFuncAttributeMaxDynamicSharedMemorySize, ATTN_SMEM);
    attn_hmma<<<dim3(SS / 128, BB * HH), 256, ATTN_SMEM>>>(qs, ks, vt, attb);

    hmma_gemm<3><<<gg, 256, GEMM_SMEM>>>(attb, wob, bo, nullptr, nullptr,
                                         d_out, nullptr, nullptr);
}

// round 15
// speedup vs baseline: 1.2865x; 1.1346x over previous
#include <cuda_runtime.h>
#include <cuda_bf16.h>
#include <cuda_fp16.h>
#include <math.h>
#include <stdint.h>

#define BB 4
#define DM 1024
#define SS 2048
#define HH 16
#define HD 64
#define K2 2048   // bf16 split rows [hi|lo] (attention out -> Wo GEMM)
#define K2H 2048  // fp16 split rows [ah|al] (x -> QKV GEMM)
#define QW 64     // Q rows: 64 fp16
#define KW 128    // K/V rows: [hi64|lo64] fp16

// ---------------- scratch (device globals; allocation-free) ----------------
__device__ __half g_xTh[(size_t)BB * SS * K2H];        // [ah|al] fp16
__device__ __half g_Wqkv[(size_t)3 * DM * DM];         // single fp16 rows (1024)
__device__ __nv_bfloat16 g_Wob[(size_t)DM * K2];       // [wh|wl] bf16
__device__ __half g_Qs[(size_t)BB * HH * SS * QW];     // fp16, x(log2e/8)
__device__ __half g_Ks[(size_t)BB * HH * SS * KW];     // [kh|kl] fp16
__device__ __half g_Vt[(size_t)BB * HH * 32 * HD * KW]; // V^T [vh|vl] fp16
__device__ __nv_bfloat16 g_attbig[(size_t)BB * SS * K2];

// ---------------- helpers ----------------
__device__ __forceinline__ uint32_t smem_u32(const void* p) {
    uint32_t a;
    asm("{ .reg .u64 t; cvta.to.shared.u64 t, %1; cvt.u32.u64 %0, t; }" : "=r"(a) : "l"(p));
    return a;
}
__device__ __forceinline__ void cp16(uint32_t s, const void* g) {
    asm volatile("cp.async.cg.shared.global [%0], [%1], 16;" :: "r"(s), "l"(g) : "memory");
}
#define CP_COMMIT() asm volatile("cp.async.commit_group;" ::: "memory")
#define CP_WAIT1()  asm volatile("cp.async.wait_group 1;" ::: "memory")
#define CP_WAIT0()  asm volatile("cp.async.wait_group 0;" ::: "memory")

__device__ __forceinline__ void ldsm4(uint32_t* r, uint32_t addr) {
    asm volatile("ldmatrix.sync.aligned.m8n8.x4.shared.b16 {%0,%1,%2,%3}, [%4];"
                 : "=r"(r[0]), "=r"(r[1]), "=r"(r[2]), "=r"(r[3]) : "r"(addr));
}
__device__ __forceinline__ void mma16816(float* c, const uint32_t* a,
                                         uint32_t b0, uint32_t b1) {
    asm volatile("mma.sync.aligned.m16n8k16.row.col.f32.bf16.bf16.f32 "
                 "{%0,%1,%2,%3}, {%4,%5,%6,%7}, {%8,%9}, {%0,%1,%2,%3};"
                 : "+f"(c[0]), "+f"(c[1]), "+f"(c[2]), "+f"(c[3])
                 : "r"(a[0]), "r"(a[1]), "r"(a[2]), "r"(a[3]), "r"(b0), "r"(b1));
}
__device__ __forceinline__ void mma16816h(float* c, const uint32_t* a,
                                          uint32_t b0, uint32_t b1) {
    asm volatile("mma.sync.aligned.m16n8k16.row.col.f32.f16.f16.f32 "
                 "{%0,%1,%2,%3}, {%4,%5,%6,%7}, {%8,%9}, {%0,%1,%2,%3};"
                 : "+f"(c[0]), "+f"(c[1]), "+f"(c[2]), "+f"(c[3])
                 : "r"(a[0]), "r"(a[1]), "r"(a[2]), "r"(a[3]), "r"(b0), "r"(b1));
}
__device__ __forceinline__ float ex2(float x) {
    float y;
    asm("ex2.approx.f32 %0, %1;" : "=f"(y) : "f"(x));
    return y;
}
__device__ __forceinline__ void split2(float v, __nv_bfloat16& hi, __nv_bfloat16& lo) {
    hi = __float2bfloat16(v);
    lo = __float2bfloat16(v - __bfloat162float(hi));
}
__device__ __forceinline__ uint32_t packhi(float a, float b) {
    return __byte_perm(__float_as_uint(a), __float_as_uint(b), 0x7632);
}
__device__ __forceinline__ float lopart(float v) {
    return v - __uint_as_float(__float_as_uint(v) & 0xFFFF0000u);
}
__device__ __forceinline__ uint32_t packlo2(float l0, float l1) {
    uint32_t r;
    asm("cvt.rn.bf16x2.f32 %0, %1, %2;" : "=r"(r) : "f"(l1), "f"(l0));
    return r;
}
__device__ __forceinline__ uint32_t pack2h(float a, float b) {
    uint32_t r;
    asm("cvt.rn.f16x2.f32 %0, %1, %2;" : "=r"(r) : "f"(b), "f"(a));
    return r;
}
__device__ __forceinline__ void split2h(float v, __half& hi, __half& lo) {
    hi = __float2half_rn(v);
    lo = __float2half_rn(v - __half2float(hi));
}

// ---------------------------------------------------------------------------
// Kernel 1: x[B,D,S] + PE -> xTh rows [ah | al] fp16
// ---------------------------------------------------------------------------
__global__ void pe_transpose_split(const float* __restrict__ x,
                                   __half* __restrict__ out) {
    __shared__ float tile[32][33];
    int b = blockIdx.z;
    int d0 = blockIdx.y * 32, s0 = blockIdx.x * 32;
    int d = d0 + threadIdx.y, s = s0 + threadIdx.x;
    float denom = expf((float)(d & ~1) * (-9.210340371976184f / (float)DM));
    float ang = (float)s * denom;
    float pe = (d & 1) ? cosf(ang) : sinf(ang);
    tile[threadIdx.y][threadIdx.x] = x[((size_t)b * DM + d) * SS + s] + pe;
    __syncthreads();
    int s2 = s0 + threadIdx.y, d2 = d0 + threadIdx.x;
    float v = tile[threadIdx.x][threadIdx.y];
    __half hi, lo; split2h(v, hi, lo);
    size_t base = ((size_t)b * SS + s2) * K2H;
    out[base + d2] = hi;
    out[base + 1024 + d2] = lo;
}

// ---------------------------------------------------------------------------
// Kernel 1b: weights. Wq/Wk/Wv -> single fp16 rows; Wo -> bf16 split rows.
// ---------------------------------------------------------------------------
__global__ void wsplit_kernel(const float* __restrict__ w0, const float* __restrict__ w1,
                              const float* __restrict__ w2, const float* __restrict__ w3,
                              __half* oqkv, __nv_bfloat16* oo) {
    int idx = blockIdx.x * 256 + threadIdx.x;
    int which = blockIdx.y;
    if (which < 3) {
        const float* src = (which == 0) ? w0 : (which == 1) ? w1 : w2;
        oqkv[(size_t)which * DM * DM + idx] = __float2half_rn(src[idx]);
    } else {
        int n = idx >> 10, dcol = idx & 1023;
        __nv_bfloat16 hi, lo; split2(w3[idx], hi, lo);
        size_t base = (size_t)n * K2;
        oo[base + dcol] = hi;
        oo[base + 1024 + dcol] = lo;
    }
}

// ---------------------------------------------------------------------------
// Kernel 2a: fp16 2-pass QKV GEMM.  C = (ah + al) · w,  N = 3072 fused.
// Stage: [Ah | Al | W] 3 x 10240 B. Epilogues emit fp16 attention layouts.
// ---------------------------------------------------------------------------
#define STGQ 30720
#define GEMM_SMEM 66048  // epilogue 128*129*4 dominates
#define QSCALE 0.18033688011112042f  // 0.125 * log2(e)

__global__ __launch_bounds__(256, 2)
void hmma_qkv(const __half* __restrict__ A, const __half* __restrict__ W,
              const float* __restrict__ bq, const float* __restrict__ bk,
              const float* __restrict__ bv,
              __half* __restrict__ outQ, __half* __restrict__ outK,
              __half* __restrict__ outV) {
    extern __shared__ char smem[];
    const uint32_t sb = smem_u32(smem);
    const int tid = threadIdx.x, wid = tid >> 5, lane = tid & 31;
    const int wr = wid >> 1, wc = wid & 1;
    const int mBase = blockIdx.y * 128, nBase = blockIdx.x * 128;

    float acc[2][8][4];
#pragma unroll
    for (int i = 0; i < 2; i++)
#pragma unroll
        for (int j = 0; j < 8; j++)
#pragma unroll
            for (int r = 0; r < 4; r++) acc[i][j][r] = 0.f;

    const int r0 = tid >> 2, c4 = tid & 3;
    const __half* gA = A + (size_t)(mBase + r0) * K2H + c4 * 8;
    const __half* gW = W + (size_t)(nBase + r0) * DM + c4 * 8;

#define LOAD_CHUNKQ(c, st)                                                    \
    do {                                                                      \
        uint32_t s0 = sb + (st) * STGQ + r0 * 80 + c4 * 16;                   \
        cp16(s0,                 gA + (c) * 32);                              \
        cp16(s0 + 64 * 80,       gA + (size_t)64 * K2H + (c) * 32);           \
        cp16(s0 + 10240,         gA + 1024 + (c) * 32);                       \
        cp16(s0 + 10240 + 64*80, gA + (size_t)64 * K2H + 1024 + (c) * 32);    \
        cp16(s0 + 20480,         gW + (c) * 32);                              \
        cp16(s0 + 20480 + 64*80, gW + (size_t)64 * DM + (c) * 32);            \
        CP_COMMIT();                                                          \
    } while (0)

    LOAD_CHUNKQ(0, 0);
    LOAD_CHUNKQ(1, 1);

    const uint32_t aB = (wr * 32 + (lane & 15)) * 80 + (lane >> 4) * 16;
    const uint32_t bB = 20480 + (wc * 64 + (lane & 15)) * 80 + (lane >> 4) * 16;

    const int NCH = 1024 / 32;  // 32
    for (int c = 0; c < NCH; c++) {
        if (c == NCH - 1) CP_WAIT0(); else CP_WAIT1();
        __syncthreads();
        const uint32_t stg = sb + (c & 1) * STGQ;
#pragma unroll
        for (int ks = 0; ks < 2; ks++) {
            uint32_t ah[2][4], al[2][4], bw[4][4];
            ldsm4(ah[0], stg + aB + ks * 32);
            ldsm4(ah[1], stg + aB + 16 * 80 + ks * 32);
            ldsm4(al[0], stg + aB + 10240 + ks * 32);
            ldsm4(al[1], stg + aB + 10240 + 16 * 80 + ks * 32);
#pragma unroll
            for (int j2 = 0; j2 < 4; j2++)
                ldsm4(bw[j2], stg + bB + j2 * 16 * 80 + ks * 32);
#pragma unroll
            for (int mi = 0; mi < 2; mi++)
#pragma unroll
                for (int nj = 0; nj < 8; nj++) {
                    uint32_t b0 = bw[nj >> 1][nj & 1], b1 = bw[nj >> 1][(nj & 1) + 2];
                    mma16816h(acc[mi][nj], ah[mi], b0, b1);
                    mma16816h(acc[mi][nj], al[mi], b0, b1);
                }
        }
        __syncthreads();
        if (c + 2 < NCH) LOAD_CHUNKQ(c + 2, c & 1);
    }
#undef LOAD_CHUNKQ

    __syncthreads();
    float* ep = (float*)smem;
#pragma unroll
    for (int mi = 0; mi < 2; mi++)
#pragma unroll
        for (int nj = 0; nj < 8; nj++) {
            int row = wr * 32 + mi * 16 + (lane >> 2);
            int col = wc * 64 + nj * 8 + (lane & 3) * 2;
            ep[row * 129 + col] = acc[mi][nj][0];
            ep[row * 129 + col + 1] = acc[mi][nj][1];
            ep[(row + 8) * 129 + col] = acc[mi][nj][2];
            ep[(row + 8) * 129 + col + 1] = acc[mi][nj][3];
        }
    __syncthreads();

    if (nBase >= 2048) {
        // V^T: [bh, chunk, d, [vh64|vl64]] fp16; coalesced uint4 stores.
        int b = mBase >> 11, s0 = mBase & 2047;
#pragma unroll
        for (int it = 0; it < 8; it++) {
            int t = tid + it * 256;
            int dl = t >> 4;
            int rem = t & 15;
            int ch = rem >> 3, jb = (rem & 7) * 8;
            int n = nBase - 2048 + dl;
            int h = n >> 6, dd = n & 63;
            float bn = bv[n];
            size_t vb = (((size_t)(b * HH + h)) * 32 + (s0 >> 6) + ch) * (64 * KW)
                        + (size_t)dd * KW;
            uint32_t hp[4], lp[4];
#pragma unroll
            for (int j2 = 0; j2 < 4; j2++) {
                float v0 = ep[(ch * 64 + jb + 2 * j2) * 129 + dl] + bn;
                float v1 = ep[(ch * 64 + jb + 2 * j2 + 1) * 129 + dl] + bn;
                __half h0, l0, h1, l1;
                split2h(v0, h0, l0); split2h(v1, h1, l1);
                hp[j2] = (uint32_t)__half_as_ushort(h0) |
                         ((uint32_t)__half_as_ushort(h1) << 16);
                lp[j2] = (uint32_t)__half_as_ushort(l0) |
                         ((uint32_t)__half_as_ushort(l1) << 16);
            }
            *(uint4*)&outV[vb + jb] = *(uint4*)&hp[0];
            *(uint4*)&outV[vb + 64 + jb] = *(uint4*)&lp[0];
        }
    } else if (nBase >= 1024) {
        // K: rows [kh64|kl64] fp16
#pragma unroll
        for (int i = 0; i < 8; i++) {
            int r = (tid >> 4) + i * 16;
            int cc = (tid & 15) * 8;
            int m = mBase + r, b = m >> 11, s = m & 2047;
            int n = nBase - 1024 + cc, h = n >> 6, dd = n & 63;
            size_t base = ((size_t)(b * HH + h) * SS + s) * KW;
            uint32_t hp[4], lp[4];
#pragma unroll
            for (int j2 = 0; j2 < 4; j2++) {
                float v0 = ep[r * 129 + cc + 2 * j2] + bk[n + 2 * j2];
                float v1 = ep[r * 129 + cc + 2 * j2 + 1] + bk[n + 2 * j2 + 1];
                __half h0, l0, h1, l1;
                split2h(v0, h0, l0); split2h(v1, h1, l1);
                hp[j2] = (uint32_t)__half_as_ushort(h0) |
                         ((uint32_t)__half_as_ushort(h1) << 16);
                lp[j2] = (uint32_t)__half_as_ushort(l0) |
                         ((uint32_t)__half_as_ushort(l1) << 16);
            }
            *(uint4*)&outK[base + dd] = *(uint4*)&hp[0];
            *(uint4*)&outK[base + 64 + dd] = *(uint4*)&lp[0];
        }
    } else {
        // Q: rows of 64 fp16, xQSCALE
#pragma unroll
        for (int i = 0; i < 8; i++) {
            int r = (tid >> 4) + i * 16;
            int cc = (tid & 15) * 8;
            int m = mBase + r, b = m >> 11, s = m & 2047;
            int n = nBase + cc, h = n >> 6, dd = n & 63;
            size_t base = ((size_t)(b * HH + h) * SS + s) * QW;
            uint32_t qp[4];
#pragma unroll
            for (int j2 = 0; j2 < 4; j2++) {
                float v0 = (ep[r * 129 + cc + 2 * j2] + bq[n + 2 * j2]) * QSCALE;
                float v1 = (ep[r * 129 + cc + 2 * j2 + 1] + bq[n + 2 * j2 + 1]) * QSCALE;
                qp[j2] = pack2h(v0, v1);
            }
            *(uint4*)&outQ[base + dd] = *(uint4*)&qp[0];
        }
    }
}

// ---------------------------------------------------------------------------
// Kernel 2b: bf16 3-pass output GEMM (attbig x Wob -> fp32 [B,D,S])
// ---------------------------------------------------------------------------
#define STG 40960
#define GEMMO_SMEM 81920

__global__ __launch_bounds__(256, 2)
void hmma_out(const __nv_bfloat16* __restrict__ A, const __nv_bfloat16* __restrict__ W,
              const float* __restrict__ bias, float* __restrict__ out) {
    extern __shared__ char smem[];
    const uint32_t sb = smem_u32(smem);
    const int tid = threadIdx.x, wid = tid >> 5, lane = tid & 31;
    const int wr = wid >> 1, wc = wid & 1;
    const int mBase = blockIdx.y * 128, nBase = blockIdx.x * 128;

    float acc[2][8][4];
#pragma unroll
    for (int i = 0; i < 2; i++)
#pragma unroll
        for (int j = 0; j < 8; j++)
#pragma unroll
            for (int r = 0; r < 4; r++) acc[i][j][r] = 0.f;

    const int r0 = tid >> 2, c4 = tid & 3;
    const __nv_bfloat16* gA = A + (size_t)(mBase + r0) * K2 + c4 * 8;
    const __nv_bfloat16* gW = W + (size_t)(nBase + r0) * K2 + c4 * 8;

#define LOAD_CHUNK(c, st)                                                     \
    do {                                                                      \
        uint32_t s0 = sb + (st) * STG + r0 * 80 + c4 * 16;                    \
        cp16(s0,                 gA + (c) * 32);                              \
        cp16(s0 + 64 * 80,       gA + (size_t)64 * K2 + (c) * 32);            \
        cp16(s0 + 10240,         gA + 1024 + (c) * 32);                       \
        cp16(s0 + 10240 + 64*80, gA + (size_t)64 * K2 + 1024 + (c) * 32);     \
        cp16(s0 + 20480,         gW + (c) * 32);                              \
        cp16(s0 + 20480 + 64*80, gW + (size_t)64 * K2 + (c) * 32);            \
        cp16(s0 + 30720,         gW + 1024 + (c) * 32);                       \
        cp16(s0 + 30720 + 64*80, gW + (size_t)64 * K2 + 1024 + (c) * 32);     \
        CP_COMMIT();                                                          \
    } while (0)

    LOAD_CHUNK(0, 0);
    LOAD_CHUNK(1, 1);

    const uint32_t aB = (wr * 32 + (lane & 15)) * 80 + (lane >> 4) * 16;
    const uint32_t bB = 20480 + (wc * 64 + (lane & 15)) * 80 + (lane >> 4) * 16;

    const int NCH = 1024 / 32;
    for (int c = 0; c < NCH; c++) {
        if (c == NCH - 1) CP_WAIT0(); else CP_WAIT1();
        __syncthreads();
        const uint32_t stg = sb + (c & 1) * STG;
#pragma unroll
        for (int ks = 0; ks < 2; ks++) {
            uint32_t ah[2][4], al[2][4], bh[4][4], bl[4][4];
            ldsm4(ah[0], stg + aB + ks * 32);
            ldsm4(ah[1], stg + aB + 16 * 80 + ks * 32);
            ldsm4(al[0], stg + aB + 10240 + ks * 32);
            ldsm4(al[1], stg + aB + 10240 + 16 * 80 + ks * 32);
#pragma unroll
            for (int j2 = 0; j2 < 4; j2++) {
                ldsm4(bh[j2], stg + bB + j2 * 16 * 80 + ks * 32);
                ldsm4(bl[j2], stg + bB + 10240 + j2 * 16 * 80 + ks * 32);
            }
#pragma unroll
            for (int mi = 0; mi < 2; mi++)
#pragma unroll
                for (int nj = 0; nj < 8; nj++) {
                    uint32_t b0 = bh[nj >> 1][nj & 1], b1 = bh[nj >> 1][(nj & 1) + 2];
                    mma16816(acc[mi][nj], ah[mi], b0, b1);
                    mma16816(acc[mi][nj], al[mi], b0, b1);
                    mma16816(acc[mi][nj], ah[mi],
                             bl[nj >> 1][nj & 1], bl[nj >> 1][(nj & 1) + 2]);
                }
        }
        __syncthreads();
        if (c + 2 < NCH) LOAD_CHUNK(c + 2, c & 1);
    }
#undef LOAD_CHUNK

    __syncthreads();
    float* ep = (float*)smem;
#pragma unroll
    for (int mi = 0; mi < 2; mi++)
#pragma unroll
        for (int nj = 0; nj < 8; nj++) {
            int row = wr * 32 + mi * 16 + (lane >> 2);
            int col = wc * 64 + nj * 8 + (lane & 3) * 2;
            ep[row * 129 + col] = acc[mi][nj][0];
            ep[row * 129 + col + 1] = acc[mi][nj][1];
            ep[(row + 8) * 129 + col] = acc[mi][nj][2];
            ep[(row + 8) * 129 + col + 1] = acc[mi][nj][3];
        }
    __syncthreads();

    int nl = tid >> 1;
    int n = nBase + nl;
    float bn = bias[n];
#pragma unroll
    for (int ii = 0; ii < 16; ii++) {
        int sl = (tid & 1) * 64 + ii * 4;
        int m0 = mBase + sl, b = m0 >> 11, s = m0 & 2047;
        float4 v;
        v.x = ep[(sl + 0) * 129 + nl] + bn;
        v.y = ep[(sl + 1) * 129 + nl] + bn;
        v.z = ep[(sl + 2) * 129 + nl] + bn;
        v.w = ep[(sl + 3) * 129 + nl] + bn;
        *(float4*)&out[((size_t)b * DM + n) * SS + s] = v;
    }
}

// ---------------------------------------------------------------------------
// Kernel 3: fp16 HMMA flash attention (unchanged from R14).
// ---------------------------------------------------------------------------
#define QPITCH 144
#define AQSZ (128 * QPITCH)
#define KVPITCH 272
#define AKVT (64 * KVPITCH)
#define ASTG (2 * AKVT)
#define ATTN_SMEM (AQSZ + 2 * ASTG)  // 88064

__device__ __forceinline__ void load_kv(uint32_t sb, int tid,
                                        const __half* Kg, const __half* Vg,
                                        int kt, int st) {
#pragma unroll
    for (int i = 0; i < 8; i++) {
        int idx = tid + i * 256;
        int t = idx >= 1024;
        int j = idx - t * 1024;
        int r = j >> 4, seg = j & 15;
        uint32_t so = AQSZ + st * ASTG + t * AKVT + r * KVPITCH + seg * 16;
        size_t go = ((size_t)kt * 64 + r) * KW + seg * 8;
        cp16(sb + so, (t ? Vg : Kg) + go);
    }
    CP_COMMIT();
}

__global__ __launch_bounds__(256, 2)
void attn_hmma(const __half* __restrict__ Qs, const __half* __restrict__ Ks,
               const __half* __restrict__ Vt, __nv_bfloat16* __restrict__ O) {
    extern __shared__ char smem[];
    const uint32_t sb = smem_u32(smem);
    const int tid = threadIdx.x, w = tid >> 5, lane = tid & 31;
    const int bh = blockIdx.y;
    const int q0 = blockIdx.x * 128;
    const __half* Qg = Qs + ((size_t)bh * SS + q0) * QW;
    const __half* Kg = Ks + (size_t)bh * SS * KW;
    const __half* Vg = Vt + (size_t)bh * (32 * 64 * KW);

#pragma unroll
    for (int i = 0; i < 4; i++) {
        int idx = tid + i * 256;
        int row = idx >> 3, seg = idx & 7;
        cp16(sb + row * QPITCH + seg * 16, Qg + (size_t)row * QW + seg * 8);
    }
    load_kv(sb, tid, Kg, Vg, 0, 0);
    load_kv(sb, tid, Kg, Vg, 1, 1);

    float o[8][4];
    float mi[2] = {-1e30f, -1e30f}, li[2] = {0.f, 0.f};
#pragma unroll
    for (int nj = 0; nj < 8; nj++)
#pragma unroll
        for (int r = 0; r < 4; r++) o[nj][r] = 0.f;

    const int q4 = lane & 3;
    const int r1 = w * 16 + (lane >> 2);
    const uint32_t aQ = sb + (w * 16 + (lane & 15)) * QPITCH + (lane >> 4) * 16;
    const uint32_t bKb = sb + AQSZ + (lane & 15) * KVPITCH + (lane >> 4) * 16;

    for (int kt = 0; kt < 32; kt++) {
        if (kt == 31) CP_WAIT0(); else CP_WAIT1();
        __syncthreads();
        const uint32_t stoff = (kt & 1) * ASTG;

        float sc[8][4];
#pragma unroll
        for (int nj = 0; nj < 8; nj++)
#pragma unroll
            for (int r = 0; r < 4; r++) sc[nj][r] = 0.f;
#pragma unroll
        for (int ks = 0; ks < 4; ks++) {
            uint32_t aq[4], bkh[4][4], bkl[4][4];
            ldsm4(aq, aQ + ks * 32);
#pragma unroll
            for (int j2 = 0; j2 < 4; j2++) {
                ldsm4(bkh[j2], bKb + stoff + j2 * 16 * KVPITCH + ks * 32);
                ldsm4(bkl[j2], bKb + stoff + 128 + j2 * 16 * KVPITCH + ks * 32);
            }
#pragma unroll
            for (int nj = 0; nj < 8; nj++) {
                mma16816h(sc[nj], aq, bkh[nj >> 1][nj & 1], bkh[nj >> 1][(nj & 1) + 2]);
                mma16816h(sc[nj], aq, bkl[nj >> 1][nj & 1], bkl[nj >> 1][(nj & 1) + 2]);
            }
        }

        uint32_t aPf[4][4];
#pragma unroll
        for (int rr = 0; rr < 2; rr++) {
            float mx = -1e30f;
#pragma unroll
            for (int nj = 0; nj < 8; nj++)
                mx = fmaxf(mx, fmaxf(sc[nj][rr * 2], sc[nj][rr * 2 + 1]));
            mx = fmaxf(mx, __shfl_xor_sync(0xffffffffu, mx, 1));
            mx = fmaxf(mx, __shfl_xor_sync(0xffffffffu, mx, 2));
            float mn = fmaxf(mi[rr], mx);
            float rs = 0.f;
#pragma unroll
            for (int nj = 0; nj < 8; nj++) {
                float p0 = ex2(sc[nj][rr * 2] - mn);
                float p1 = ex2(sc[nj][rr * 2 + 1] - mn);
                rs += p0 + p1;
                aPf[nj >> 1][(nj & 1) * 2 + rr] = pack2h(p0, p1);
            }
            rs += __shfl_xor_sync(0xffffffffu, rs, 1);
            rs += __shfl_xor_sync(0xffffffffu, rs, 2);
            float f = ex2(mi[rr] - mn);
            li[rr] = li[rr] * f + rs;
            mi[rr] = mn;
#pragma unroll
            for (int nj = 0; nj < 8; nj++) {
                o[nj][rr * 2] *= f;
                o[nj][rr * 2 + 1] *= f;
            }
        }

        const uint32_t bVb = bKb + AKVT + stoff;
#pragma unroll
        for (int kk = 0; kk < 4; kk++) {
            uint32_t bvh[4][4], bvl[4][4];
#pragma unroll
            for (int j2 = 0; j2 < 4; j2++) {
                ldsm4(bvh[j2], bVb + j2 * 16 * KVPITCH + kk * 32);
                ldsm4(bvl[j2], bVb + 128 + j2 * 16 * KVPITCH + kk * 32);
            }
#pragma unroll
            for (int nj = 0; nj < 8; nj++) {
                mma16816h(o[nj], aPf[kk], bvh[nj >> 1][nj & 1], bvh[nj >> 1][(nj & 1) + 2]);
                mma16816h(o[nj], aPf[kk], bvl[nj >> 1][nj & 1], bvl[nj >> 1][(nj & 1) + 2]);
            }
        }
        __syncthreads();
        if (kt + 2 < 32) load_kv(sb, tid, Kg, Vg, kt + 2, kt & 1);
    }

    const int b_ = bh >> 4, h_ = bh & 15;
#pragma unroll
    for (int rr = 0; rr < 2; rr++) {
        float inv = 1.f / li[rr];
        size_t base = ((size_t)b_ * SS + q0 + r1 + rr * 8) * (size_t)K2;
#pragma unroll
        for (int nj = 0; nj < 8; nj++) {
            int d = nj * 8 + 2 * q4;
            float v0 = o[nj][rr * 2] * inv, v1 = o[nj][rr * 2 + 1] * inv;
            *(uint32_t*)&O[base + h_ * 64 + d] = packhi(v0, v1);
            *(uint32_t*)&O[base + 1024 + h_ * 64 + d] = packlo2(lopart(v0), lopart(v1));
        }
    }
}

// ---------------------------------------------------------------------------
extern "C" void kernel_launch(void* const* d_in, const int* in_sizes, int n_in,
                              void* d_out, int out_size) {
    const float* x  = (const float*)d_in[0];
    const float* Wq = (const float*)d_in[1];
    const float* bq = (const float*)d_in[2];
    const float* Wk = (const float*)d_in[3];
    const float* bk = (const float*)d_in[4];
    const float* Wv = (const float*)d_in[5];
    const float* bv = (const float*)d_in[6];
    const float* Wo = (const float*)d_in[7];
    const float* bo = (const float*)d_in[8];

    __half *xTh, *wqkv, *qs, *ks, *vt;
    __nv_bfloat16 *wob, *attb;
    cudaGetSymbolAddress((void**)&xTh, g_xTh);
    cudaGetSymbolAddress((void**)&wqkv, g_Wqkv);
    cudaGetSymbolAddress((void**)&wob, g_Wob);
    cudaGetSymbolAddress((void**)&qs, g_Qs);
    cudaGetSymbolAddress((void**)&ks, g_Ks);
    cudaGetSymbolAddress((void**)&vt, g_Vt);
    cudaGetSymbolAddress((void**)&attb, g_attbig);

    pe_transpose_split<<<dim3(SS / 32, DM / 32, BB), dim3(32, 32)>>>(x, xTh);
    wsplit_kernel<<<dim3(DM * DM / 256, 4), 256>>>(Wq, Wk, Wv, Wo, wqkv, wob);

    cudaFuncSetAttribute(hmma_qkv, cudaFuncAttributeMaxDynamicSharedMemorySize, GEMM_SMEM);
    cudaFuncSetAttribute(hmma_out, cudaFuncAttributeMaxDynamicSharedMemorySize, GEMMO_SMEM);
    dim3 ggQKV(3 * DM / 128, (BB * SS) / 128);  // (24, 64)
    dim3 gg(DM / 128, (BB * SS) / 128);         // (8, 64)
    hmma_qkv<<<ggQKV, 256, GEMM_SMEM>>>(xTh, wqkv, bq, bk, bv, qs, ks, vt);

    cudaFuncSetAttribute(attn_hmma, cudaFuncAttributeMaxDynamicSharedMemorySize, ATTN_SMEM);
    attn_hmma<<<dim3(SS / 128, BB * HH), 256, ATTN_SMEM>>>(qs, ks, vt, attb);

    hmma_out<<<gg, 256, GEMMO_SMEM>>>(attb, wob, bo, (float*)d_out);
}

// round 16
// speedup vs baseline: 1.6204x; 1.2596x over previous
#include <cuda_runtime.h>
#include <cuda_bf16.h>
#include <cuda_fp16.h>
#include <math.h>
#include <stdint.h>

#define BB 4
#define DM 1024
#define SS 2048
#define HH 16
#define HD 64
#define K2 2048   // Wo-GEMM A rows: [ah x1024 | al x1024] fp16
#define QW 64     // Q rows: 64 fp16
#define KW 128    // K/V rows: [hi64|lo64] fp16

// ---------------- scratch (device globals; allocation-free) ----------------
__device__ __half g_xTh[(size_t)BB * SS * DM];          // single fp16 rows
__device__ __half g_Wqkv[(size_t)3 * DM * DM];          // single fp16 rows
__device__ __half g_Wo1[(size_t)DM * DM];               // single fp16 rows
__device__ __half g_Qs[(size_t)BB * HH * SS * QW];      // fp16, x(log2e/8)
__device__ __half g_Ks[(size_t)BB * HH * SS * KW];      // [kh|kl] fp16
__device__ __half g_Vt[(size_t)BB * HH * 32 * HD * KW]; // V^T [vh|vl] fp16
__device__ __half g_attbig[(size_t)BB * SS * K2];       // [ah|al] fp16

// ---------------- helpers ----------------
__device__ __forceinline__ uint32_t smem_u32(const void* p) {
    uint32_t a;
    asm("{ .reg .u64 t; cvta.to.shared.u64 t, %1; cvt.u32.u64 %0, t; }" : "=r"(a) : "l"(p));
    return a;
}
__device__ __forceinline__ void cp16(uint32_t s, const void* g) {
    asm volatile("cp.async.cg.shared.global [%0], [%1], 16;" :: "r"(s), "l"(g) : "memory");
}
#define CP_COMMIT() asm volatile("cp.async.commit_group;" ::: "memory")
#define CP_WAIT1()  asm volatile("cp.async.wait_group 1;" ::: "memory")
#define CP_WAIT0()  asm volatile("cp.async.wait_group 0;" ::: "memory")

__device__ __forceinline__ void ldsm4(uint32_t* r, uint32_t addr) {
    asm volatile("ldmatrix.sync.aligned.m8n8.x4.shared.b16 {%0,%1,%2,%3}, [%4];"
                 : "=r"(r[0]), "=r"(r[1]), "=r"(r[2]), "=r"(r[3]) : "r"(addr));
}
__device__ __forceinline__ void mma16816h(float* c, const uint32_t* a,
                                          uint32_t b0, uint32_t b1) {
    asm volatile("mma.sync.aligned.m16n8k16.row.col.f32.f16.f16.f32 "
                 "{%0,%1,%2,%3}, {%4,%5,%6,%7}, {%8,%9}, {%0,%1,%2,%3};"
                 : "+f"(c[0]), "+f"(c[1]), "+f"(c[2]), "+f"(c[3])
                 : "r"(a[0]), "r"(a[1]), "r"(a[2]), "r"(a[3]), "r"(b0), "r"(b1));
}
__device__ __forceinline__ float ex2(float x) {
    float y;
    asm("ex2.approx.f32 %0, %1;" : "=f"(y) : "f"(x));
    return y;
}
__device__ __forceinline__ uint32_t pack2h(float a, float b) {
    uint32_t r;
    asm("cvt.rn.f16x2.f32 %0, %1, %2;" : "=r"(r) : "f"(b), "f"(a));
    return r;  // a in low half
}
__device__ __forceinline__ void split2h(float v, __half& hi, __half& lo) {
    hi = __float2half_rn(v);
    lo = __float2half_rn(v - __half2float(hi));
}
__device__ __forceinline__ uint32_t packh(__half a, __half b) {
    return (uint32_t)__half_as_ushort(a) | ((uint32_t)__half_as_ushort(b) << 16);
}

// ---------------------------------------------------------------------------
// Kernel 1: x[B,D,S] + PE -> xTh single fp16 rows [B*S, 1024]
// ---------------------------------------------------------------------------
__global__ void pe_transpose_h(const float* __restrict__ x,
                               __half* __restrict__ out) {
    __shared__ float tile[32][33];
    int b = blockIdx.z;
    int d0 = blockIdx.y * 32, s0 = blockIdx.x * 32;
    int d = d0 + threadIdx.y, s = s0 + threadIdx.x;
    float denom = expf((float)(d & ~1) * (-9.210340371976184f / (float)DM));
    float ang = (float)s * denom;
    float pe = (d & 1) ? cosf(ang) : sinf(ang);
    tile[threadIdx.y][threadIdx.x] = x[((size_t)b * DM + d) * SS + s] + pe;
    __syncthreads();
    int s2 = s0 + threadIdx.y, d2 = d0 + threadIdx.x;
    out[((size_t)b * SS + s2) * DM + d2] = __float2half_rn(tile[threadIdx.x][threadIdx.y]);
}

// ---------------------------------------------------------------------------
// Kernel 1b: all four weights -> single fp16 rows
// ---------------------------------------------------------------------------
__global__ void wconv_kernel(const float* __restrict__ w0, const float* __restrict__ w1,
                             const float* __restrict__ w2, const float* __restrict__ w3,
                             __half* oqkv, __half* oo) {
    int idx = blockIdx.x * 256 + threadIdx.x;
    int which = blockIdx.y;
    if (which < 3) {
        const float* src = (which == 0) ? w0 : (which == 1) ? w1 : w2;
        oqkv[(size_t)which * DM * DM + idx] = __float2half_rn(src[idx]);
    } else {
        oo[idx] = __float2half_rn(w3[idx]);
    }
}

// ---------------------------------------------------------------------------
// Kernel 2a: 1-pass fp16 QKV GEMM.  C = a · w,  N = 3072 fused.
// Stage: [A | W] 2 x 10240 B. Epilogues emit fp16 attention layouts.
// ---------------------------------------------------------------------------
#define STGQ1 20480
#define GEMM_SMEM 66048  // epilogue 128*129*4 dominates
#define QSCALE 0.18033688011112042f  // 0.125 * log2(e)

__global__ __launch_bounds__(256, 2)
void hmma_qkv(const __half* __restrict__ A, const __half* __restrict__ W,
              const float* __restrict__ bq, const float* __restrict__ bk,
              const float* __restrict__ bv,
              __half* __restrict__ outQ, __half* __restrict__ outK,
              __half* __restrict__ outV) {
    extern __shared__ char smem[];
    const uint32_t sb = smem_u32(smem);
    const int tid = threadIdx.x, wid = tid >> 5, lane = tid & 31;
    const int wr = wid >> 1, wc = wid & 1;
    const int mBase = blockIdx.y * 128, nBase = blockIdx.x * 128;

    float acc[2][8][4];
#pragma unroll
    for (int i = 0; i < 2; i++)
#pragma unroll
        for (int j = 0; j < 8; j++)
#pragma unroll
            for (int r = 0; r < 4; r++) acc[i][j][r] = 0.f;

    const int r0 = tid >> 2, c4 = tid & 3;
    const __half* gA = A + (size_t)(mBase + r0) * DM + c4 * 8;
    const __half* gW = W + (size_t)(nBase + r0) * DM + c4 * 8;

#define LOAD_CHUNKQ(c, st)                                                    \
    do {                                                                      \
        uint32_t s0 = sb + (st) * STGQ1 + r0 * 80 + c4 * 16;                  \
        cp16(s0,                 gA + (c) * 32);                              \
        cp16(s0 + 64 * 80,       gA + (size_t)64 * DM + (c) * 32);            \
        cp16(s0 + 10240,         gW + (c) * 32);                              \
        cp16(s0 + 10240 + 64*80, gW + (size_t)64 * DM + (c) * 32);            \
        CP_COMMIT();                                                          \
    } while (0)

    LOAD_CHUNKQ(0, 0);
    LOAD_CHUNKQ(1, 1);

    const uint32_t aB = (wr * 32 + (lane & 15)) * 80 + (lane >> 4) * 16;
    const uint32_t bB = 10240 + (wc * 64 + (lane & 15)) * 80 + (lane >> 4) * 16;

    const int NCH = 1024 / 32;  // 32
    for (int c = 0; c < NCH; c++) {
        if (c == NCH - 1) CP_WAIT0(); else CP_WAIT1();
        __syncthreads();
        const uint32_t stg = sb + (c & 1) * STGQ1;
#pragma unroll
        for (int ks = 0; ks < 2; ks++) {
            uint32_t a[2][4], bw[4][4];
            ldsm4(a[0], stg + aB + ks * 32);
            ldsm4(a[1], stg + aB + 16 * 80 + ks * 32);
#pragma unroll
            for (int j2 = 0; j2 < 4; j2++)
                ldsm4(bw[j2], stg + bB + j2 * 16 * 80 + ks * 32);
#pragma unroll
            for (int mi = 0; mi < 2; mi++)
#pragma unroll
                for (int nj = 0; nj < 8; nj++)
                    mma16816h(acc[mi][nj], a[mi],
                              bw[nj >> 1][nj & 1], bw[nj >> 1][(nj & 1) + 2]);
        }
        __syncthreads();
        if (c + 2 < NCH) LOAD_CHUNKQ(c + 2, c & 1);
    }
#undef LOAD_CHUNKQ

    __syncthreads();
    float* ep = (float*)smem;
#pragma unroll
    for (int mi = 0; mi < 2; mi++)
#pragma unroll
        for (int nj = 0; nj < 8; nj++) {
            int row = wr * 32 + mi * 16 + (lane >> 2);
            int col = wc * 64 + nj * 8 + (lane & 3) * 2;
            ep[row * 129 + col] = acc[mi][nj][0];
            ep[row * 129 + col + 1] = acc[mi][nj][1];
            ep[(row + 8) * 129 + col] = acc[mi][nj][2];
            ep[(row + 8) * 129 + col + 1] = acc[mi][nj][3];
        }
    __syncthreads();

    if (nBase >= 2048) {
        // V^T: [bh, chunk, d, [vh64|vl64]] fp16; coalesced uint4 stores.
        int b = mBase >> 11, s0 = mBase & 2047;
#pragma unroll
        for (int it = 0; it < 8; it++) {
            int t = tid + it * 256;
            int dl = t >> 4;
            int rem = t & 15;
            int ch = rem >> 3, jb = (rem & 7) * 8;
            int n = nBase - 2048 + dl;
            int h = n >> 6, dd = n & 63;
            float bn = bv[n];
            size_t vb = (((size_t)(b * HH + h)) * 32 + (s0 >> 6) + ch) * (64 * KW)
                        + (size_t)dd * KW;
            uint32_t hp[4], lp[4];
#pragma unroll
            for (int j2 = 0; j2 < 4; j2++) {
                float v0 = ep[(ch * 64 + jb + 2 * j2) * 129 + dl] + bn;
                float v1 = ep[(ch * 64 + jb + 2 * j2 + 1) * 129 + dl] + bn;
                __half h0, l0, h1, l1;
                split2h(v0, h0, l0); split2h(v1, h1, l1);
                hp[j2] = packh(h0, h1);
                lp[j2] = packh(l0, l1);
            }
            *(uint4*)&outV[vb + jb] = *(uint4*)&hp[0];
            *(uint4*)&outV[vb + 64 + jb] = *(uint4*)&lp[0];
        }
    } else if (nBase >= 1024) {
        // K: rows [kh64|kl64] fp16
#pragma unroll
        for (int i = 0; i < 8; i++) {
            int r = (tid >> 4) + i * 16;
            int cc = (tid & 15) * 8;
            int m = mBase + r, b = m >> 11, s = m & 2047;
            int n = nBase - 1024 + cc, h = n >> 6, dd = n & 63;
            size_t base = ((size_t)(b * HH + h) * SS + s) * KW;
            uint32_t hp[4], lp[4];
#pragma unroll
            for (int j2 = 0; j2 < 4; j2++) {
                float v0 = ep[r * 129 + cc + 2 * j2] + bk[n + 2 * j2];
                float v1 = ep[r * 129 + cc + 2 * j2 + 1] + bk[n + 2 * j2 + 1];
                __half h0, l0, h1, l1;
                split2h(v0, h0, l0); split2h(v1, h1, l1);
                hp[j2] = packh(h0, h1);
                lp[j2] = packh(l0, l1);
            }
            *(uint4*)&outK[base + dd] = *(uint4*)&hp[0];
            *(uint4*)&outK[base + 64 + dd] = *(uint4*)&lp[0];
        }
    } else {
        // Q: rows of 64 fp16, xQSCALE
#pragma unroll
        for (int i = 0; i < 8; i++) {
            int r = (tid >> 4) + i * 16;
            int cc = (tid & 15) * 8;
            int m = mBase + r, b = m >> 11, s = m & 2047;
            int n = nBase + cc, h = n >> 6, dd = n & 63;
            size_t base = ((size_t)(b * HH + h) * SS + s) * QW;
            uint32_t qp[4];
#pragma unroll
            for (int j2 = 0; j2 < 4; j2++) {
                float v0 = (ep[r * 129 + cc + 2 * j2] + bq[n + 2 * j2]) * QSCALE;
                float v1 = (ep[r * 129 + cc + 2 * j2 + 1] + bq[n + 2 * j2 + 1]) * QSCALE;
                qp[j2] = pack2h(v0, v1);
            }
            *(uint4*)&outQ[base + dd] = *(uint4*)&qp[0];
        }
    }
}

// ---------------------------------------------------------------------------
// Kernel 2b: 2-pass fp16 output GEMM.  C = (ah + al) · w -> fp32 [B,D,S].
// Stage: [Ah | Al | W] 3 x 10240 B.
// ---------------------------------------------------------------------------
#define STGO 30720

__global__ __launch_bounds__(256, 2)
void hmma_out(const __half* __restrict__ A, const __half* __restrict__ W,
              const float* __restrict__ bias, float* __restrict__ out) {
    extern __shared__ char smem[];
    const uint32_t sb = smem_u32(smem);
    const int tid = threadIdx.x, wid = tid >> 5, lane = tid & 31;
    const int wr = wid >> 1, wc = wid & 1;
    const int mBase = blockIdx.y * 128, nBase = blockIdx.x * 128;

    float acc[2][8][4];
#pragma unroll
    for (int i = 0; i < 2; i++)
#pragma unroll
        for (int j = 0; j < 8; j++)
#pragma unroll
            for (int r = 0; r < 4; r++) acc[i][j][r] = 0.f;

    const int r0 = tid >> 2, c4 = tid & 3;
    const __half* gA = A + (size_t)(mBase + r0) * K2 + c4 * 8;
    const __half* gW = W + (size_t)(nBase + r0) * DM + c4 * 8;

#define LOAD_CHUNKO(c, st)                                                    \
    do {                                                                      \
        uint32_t s0 = sb + (st) * STGO + r0 * 80 + c4 * 16;                   \
        cp16(s0,                 gA + (c) * 32);                              \
        cp16(s0 + 64 * 80,       gA + (size_t)64 * K2 + (c) * 32);            \
        cp16(s0 + 10240,         gA + 1024 + (c) * 32);                       \
        cp16(s0 + 10240 + 64*80, gA + (size_t)64 * K2 + 1024 + (c) * 32);     \
        cp16(s0 + 20480,         gW + (c) * 32);                              \
        cp16(s0 + 20480 + 64*80, gW + (size_t)64 * DM + (c) * 32);            \
        CP_COMMIT();                                                          \
    } while (0)

    LOAD_CHUNKO(0, 0);
    LOAD_CHUNKO(1, 1);

    const uint32_t aB = (wr * 32 + (lane & 15)) * 80 + (lane >> 4) * 16;
    const uint32_t bB = 20480 + (wc * 64 + (lane & 15)) * 80 + (lane >> 4) * 16;

    const int NCH = 1024 / 32;
    for (int c = 0; c < NCH; c++) {
        if (c == NCH - 1) CP_WAIT0(); else CP_WAIT1();
        __syncthreads();
        const uint32_t stg = sb + (c & 1) * STGO;
#pragma unroll
        for (int ks = 0; ks < 2; ks++) {
            uint32_t ah[2][4], al[2][4], bw[4][4];
            ldsm4(ah[0], stg + aB + ks * 32);
            ldsm4(ah[1], stg + aB + 16 * 80 + ks * 32);
            ldsm4(al[0], stg + aB + 10240 + ks * 32);
            ldsm4(al[1], stg + aB + 10240 + 16 * 80 + ks * 32);
#pragma unroll
            for (int j2 = 0; j2 < 4; j2++)
                ldsm4(bw[j2], stg + bB + j2 * 16 * 80 + ks * 32);
#pragma unroll
            for (int mi = 0; mi < 2; mi++)
#pragma unroll
                for (int nj = 0; nj < 8; nj++) {
                    uint32_t b0 = bw[nj >> 1][nj & 1], b1 = bw[nj >> 1][(nj & 1) + 2];
                    mma16816h(acc[mi][nj], ah[mi], b0, b1);
                    mma16816h(acc[mi][nj], al[mi], b0, b1);
                }
        }
        __syncthreads();
        if (c + 2 < NCH) LOAD_CHUNKO(c + 2, c & 1);
    }
#undef LOAD_CHUNKO

    __syncthreads();
    float* ep = (float*)smem;
#pragma unroll
    for (int mi = 0; mi < 2; mi++)
#pragma unroll
        for (int nj = 0; nj < 8; nj++) {
            int row = wr * 32 + mi * 16 + (lane >> 2);
            int col = wc * 64 + nj * 8 + (lane & 3) * 2;
            ep[row * 129 + col] = acc[mi][nj][0];
            ep[row * 129 + col + 1] = acc[mi][nj][1];
            ep[(row + 8) * 129 + col] = acc[mi][nj][2];
            ep[(row + 8) * 129 + col + 1] = acc[mi][nj][3];
        }
    __syncthreads();

    int nl = tid >> 1;
    int n = nBase + nl;
    float bn = bias[n];
#pragma unroll
    for (int ii = 0; ii < 16; ii++) {
        int sl = (tid & 1) * 64 + ii * 4;
        int m0 = mBase + sl, b = m0 >> 11, s = m0 & 2047;
        float4 v;
        v.x = ep[(sl + 0) * 129 + nl] + bn;
        v.y = ep[(sl + 1) * 129 + nl] + bn;
        v.z = ep[(sl + 2) * 129 + nl] + bn;
        v.w = ep[(sl + 3) * 129 + nl] + bn;
        *(float4*)&out[((size_t)b * DM + n) * SS + s] = v;
    }
}

// ---------------------------------------------------------------------------
// Kernel 3: fp16 HMMA flash attention (mainloop unchanged from R14/15).
// Epilogue now emits fp16 split rows [ah|al] for the Wo GEMM.
// ---------------------------------------------------------------------------
#define QPITCH 144
#define AQSZ (128 * QPITCH)
#define KVPITCH 272
#define AKVT (64 * KVPITCH)
#define ASTG (2 * AKVT)
#define ATTN_SMEM (AQSZ + 2 * ASTG)  // 88064

__device__ __forceinline__ void load_kv(uint32_t sb, int tid,
                                        const __half* Kg, const __half* Vg,
                                        int kt, int st) {
#pragma unroll
    for (int i = 0; i < 8; i++) {
        int idx = tid + i * 256;
        int t = idx >= 1024;
        int j = idx - t * 1024;
        int r = j >> 4, seg = j & 15;
        uint32_t so = AQSZ + st * ASTG + t * AKVT + r * KVPITCH + seg * 16;
        size_t go = ((size_t)kt * 64 + r) * KW + seg * 8;
        cp16(sb + so, (t ? Vg : Kg) + go);
    }
    CP_COMMIT();
}

__global__ __launch_bounds__(256, 2)
void attn_hmma(const __half* __restrict__ Qs, const __half* __restrict__ Ks,
               const __half* __restrict__ Vt, __half* __restrict__ O) {
    extern __shared__ char smem[];
    const uint32_t sb = smem_u32(smem);
    const int tid = threadIdx.x, w = tid >> 5, lane = tid & 31;
    const int bh = blockIdx.y;
    const int q0 = blockIdx.x * 128;
    const __half* Qg = Qs + ((size_t)bh * SS + q0) * QW;
    const __half* Kg = Ks + (size_t)bh * SS * KW;
    const __half* Vg = Vt + (size_t)bh * (32 * 64 * KW);

#pragma unroll
    for (int i = 0; i < 4; i++) {
        int idx = tid + i * 256;
        int row = idx >> 3, seg = idx & 7;
        cp16(sb + row * QPITCH + seg * 16, Qg + (size_t)row * QW + seg * 8);
    }
    load_kv(sb, tid, Kg, Vg, 0, 0);
    load_kv(sb, tid, Kg, Vg, 1, 1);

    float o[8][4];
    float mi[2] = {-1e30f, -1e30f}, li[2] = {0.f, 0.f};
#pragma unroll
    for (int nj = 0; nj < 8; nj++)
#pragma unroll
        for (int r = 0; r < 4; r++) o[nj][r] = 0.f;

    const int q4 = lane & 3;
    const int r1 = w * 16 + (lane >> 2);
    const uint32_t aQ = sb + (w * 16 + (lane & 15)) * QPITCH + (lane >> 4) * 16;
    const uint32_t bKb = sb + AQSZ + (lane & 15) * KVPITCH + (lane >> 4) * 16;

    for (int kt = 0; kt < 32; kt++) {
        if (kt == 31) CP_WAIT0(); else CP_WAIT1();
        __syncthreads();
        const uint32_t stoff = (kt & 1) * ASTG;

        float sc[8][4];
#pragma unroll
        for (int nj = 0; nj < 8; nj++)
#pragma unroll
            for (int r = 0; r < 4; r++) sc[nj][r] = 0.f;
#pragma unroll
        for (int ks = 0; ks < 4; ks++) {
            uint32_t aq[4], bkh[4][4], bkl[4][4];
            ldsm4(aq, aQ + ks * 32);
#pragma unroll
            for (int j2 = 0; j2 < 4; j2++) {
                ldsm4(bkh[j2], bKb + stoff + j2 * 16 * KVPITCH + ks * 32);
                ldsm4(bkl[j2], bKb + stoff + 128 + j2 * 16 * KVPITCH + ks * 32);
            }
#pragma unroll
            for (int nj = 0; nj < 8; nj++) {
                mma16816h(sc[nj], aq, bkh[nj >> 1][nj & 1], bkh[nj >> 1][(nj & 1) + 2]);
                mma16816h(sc[nj], aq, bkl[nj >> 1][nj & 1], bkl[nj >> 1][(nj & 1) + 2]);
            }
        }

        uint32_t aPf[4][4];
#pragma unroll
        for (int rr = 0; rr < 2; rr++) {
            float mx = -1e30f;
#pragma unroll
            for (int nj = 0; nj < 8; nj++)
                mx = fmaxf(mx, fmaxf(sc[nj][rr * 2], sc[nj][rr * 2 + 1]));
            mx = fmaxf(mx, __shfl_xor_sync(0xffffffffu, mx, 1));
            mx = fmaxf(mx, __shfl_xor_sync(0xffffffffu, mx, 2));
            float mn = fmaxf(mi[rr], mx);
            float rs = 0.f;
#pragma unroll
            for (int nj = 0; nj < 8; nj++) {
                float p0 = ex2(sc[nj][rr * 2] - mn);
                float p1 = ex2(sc[nj][rr * 2 + 1] - mn);
                rs += p0 + p1;
                aPf[nj >> 1][(nj & 1) * 2 + rr] = pack2h(p0, p1);
            }
            rs += __shfl_xor_sync(0xffffffffu, rs, 1);
            rs += __shfl_xor_sync(0xffffffffu, rs, 2);
            float f = ex2(mi[rr] - mn);
            li[rr] = li[rr] * f + rs;
            mi[rr] = mn;
#pragma unroll
            for (int nj = 0; nj < 8; nj++) {
                o[nj][rr * 2] *= f;
                o[nj][rr * 2 + 1] *= f;
            }
        }

        const uint32_t bVb = bKb + AKVT + stoff;
#pragma unroll
        for (int kk = 0; kk < 4; kk++) {
            uint32_t bvh[4][4], bvl[4][4];
#pragma unroll
            for (int j2 = 0; j2 < 4; j2++) {
                ldsm4(bvh[j2], bVb + j2 * 16 * KVPITCH + kk * 32);
                ldsm4(bvl[j2], bVb + 128 + j2 * 16 * KVPITCH + kk * 32);
            }
#pragma unroll
            for (int nj = 0; nj < 8; nj++) {
                mma16816h(o[nj], aPf[kk], bvh[nj >> 1][nj & 1], bvh[nj >> 1][(nj & 1) + 2]);
                mma16816h(o[nj], aPf[kk], bvl[nj >> 1][nj & 1], bvl[nj >> 1][(nj & 1) + 2]);
            }
        }
        __syncthreads();
        if (kt + 2 < 32) load_kv(sb, tid, Kg, Vg, kt + 2, kt & 1);
    }

    // epilogue: normalize, emit fp16 [ah|al] rows for Wo GEMM
    const int b_ = bh >> 4, h_ = bh & 15;
#pragma unroll
    for (int rr = 0; rr < 2; rr++) {
        float inv = 1.f / li[rr];
        size_t base = ((size_t)b_ * SS + q0 + r1 + rr * 8) * (size_t)K2;
#pragma unroll
        for (int nj = 0; nj < 8; nj++) {
            int d = nj * 8 + 2 * q4;
            float v0 = o[nj][rr * 2] * inv, v1 = o[nj][rr * 2 + 1] * inv;
            __half h0, l0, h1, l1;
            split2h(v0, h0, l0); split2h(v1, h1, l1);
            *(uint32_t*)&O[base + h_ * 64 + d] = packh(h0, h1);
            *(uint32_t*)&O[base + 1024 + h_ * 64 + d] = packh(l0, l1);
        }
    }
}

// ---------------------------------------------------------------------------
extern "C" void kernel_launch(void* const* d_in, const int* in_sizes, int n_in,
                              void* d_out, int out_size) {
    const float* x  = (const float*)d_in[0];
    const float* Wq = (const float*)d_in[1];
    const float* bq = (const float*)d_in[2];
    const float* Wk = (const float*)d_in[3];
    const float* bk = (const float*)d_in[4];
    const float* Wv = (const float*)d_in[5];
    const float* bv = (const float*)d_in[6];
    const float* Wo = (const float*)d_in[7];
    const float* bo = (const float*)d_in[8];

    __half *xTh, *wqkv, *wo1, *qs, *ks, *vt, *attb;
    cudaGetSymbolAddress((void**)&xTh, g_xTh);
    cudaGetSymbolAddress((void**)&wqkv, g_Wqkv);
    cudaGetSymbolAddress((void**)&wo1, g_Wo1);
    cudaGetSymbolAddress((void**)&qs, g_Qs);
    cudaGetSymbolAddress((void**)&ks, g_Ks);
    cudaGetSymbolAddress((void**)&vt, g_Vt);
    cudaGetSymbolAddress((void**)&attb, g_attbig);

    pe_transpose_h<<<dim3(SS / 32, DM / 32, BB), dim3(32, 32)>>>(x, xTh);
    wconv_kernel<<<dim3(DM * DM / 256, 4), 256>>>(Wq, Wk, Wv, Wo, wqkv, wo1);

    cudaFuncSetAttribute(hmma_qkv, cudaFuncAttributeMaxDynamicSharedMemorySize, GEMM_SMEM);
    cudaFuncSetAttribute(hmma_out, cudaFuncAttributeMaxDynamicSharedMemorySize, GEMM_SMEM);
    dim3 ggQKV(3 * DM / 128, (BB * SS) / 128);  // (24, 64)
    dim3 gg(DM / 128, (BB * SS) / 128);         // (8, 64)
    hmma_qkv<<<ggQKV, 256, GEMM_SMEM>>>(xTh, wqkv, bq, bk, bv, qs, ks, vt);

    cudaFuncSetAttribute(attn_hmma, cudaFuncAttributeMaxDynamicSharedMemorySize, ATTN_SMEM);
    attn_hmma<<<dim3(SS / 128, BB * HH), 256, ATTN_SMEM>>>(qs, ks, vt, attb);

    hmma_out<<<gg, 256, GEMM_SMEM>>>(attb, wo1, bo, (float*)d_out);
}

// round 17
// speedup vs baseline: 2.0695x; 1.2771x over previous
#include <cuda_runtime.h>
#include <cuda_bf16.h>
#include <cuda_fp16.h>
#include <math.h>
#include <stdint.h>

#define BB 4
#define DM 1024
#define SS 2048
#define HH 16
#define HD 64
#define K2 2048   // Wo-GEMM A rows: [ah x1024 | al x1024] fp16
#define QW 64     // Q rows: 64 fp16
#define KW 64     // K/V rows: 64 fp16 (single precision fp16)

// ---------------- scratch (device globals; allocation-free) ----------------
__device__ __half g_xTh[(size_t)BB * SS * DM];          // single fp16 rows
__device__ __half g_Wqkv[(size_t)3 * DM * DM];          // single fp16 rows
__device__ __half g_Wo1[(size_t)DM * DM];               // single fp16 rows
__device__ __half g_Qs[(size_t)BB * HH * SS * QW];      // fp16, x(log2e/8)
__device__ __half g_Ks[(size_t)BB * HH * SS * KW];      // fp16
__device__ __half g_Vt[(size_t)BB * HH * 32 * HD * KW]; // V^T fp16
__device__ __half g_attbig[(size_t)BB * SS * K2];       // [ah|al] fp16

// ---------------- helpers ----------------
__device__ __forceinline__ uint32_t smem_u32(const void* p) {
    uint32_t a;
    asm("{ .reg .u64 t; cvta.to.shared.u64 t, %1; cvt.u32.u64 %0, t; }" : "=r"(a) : "l"(p));
    return a;
}
__device__ __forceinline__ void cp16(uint32_t s, const void* g) {
    asm volatile("cp.async.cg.shared.global [%0], [%1], 16;" :: "r"(s), "l"(g) : "memory");
}
#define CP_COMMIT() asm volatile("cp.async.commit_group;" ::: "memory")
#define CP_WAIT1()  asm volatile("cp.async.wait_group 1;" ::: "memory")
#define CP_WAIT0()  asm volatile("cp.async.wait_group 0;" ::: "memory")

__device__ __forceinline__ void ldsm4(uint32_t* r, uint32_t addr) {
    asm volatile("ldmatrix.sync.aligned.m8n8.x4.shared.b16 {%0,%1,%2,%3}, [%4];"
                 : "=r"(r[0]), "=r"(r[1]), "=r"(r[2]), "=r"(r[3]) : "r"(addr));
}
__device__ __forceinline__ void mma16816h(float* c, const uint32_t* a,
                                          uint32_t b0, uint32_t b1) {
    asm volatile("mma.sync.aligned.m16n8k16.row.col.f32.f16.f16.f32 "
                 "{%0,%1,%2,%3}, {%4,%5,%6,%7}, {%8,%9}, {%0,%1,%2,%3};"
                 : "+f"(c[0]), "+f"(c[1]), "+f"(c[2]), "+f"(c[3])
                 : "r"(a[0]), "r"(a[1]), "r"(a[2]), "r"(a[3]), "r"(b0), "r"(b1));
}
__device__ __forceinline__ float ex2(float x) {
    float y;
    asm("ex2.approx.f32 %0, %1;" : "=f"(y) : "f"(x));
    return y;
}
__device__ __forceinline__ uint32_t pack2h(float a, float b) {
    uint32_t r;
    asm("cvt.rn.f16x2.f32 %0, %1, %2;" : "=r"(r) : "f"(b), "f"(a));
    return r;  // a in low half
}
__device__ __forceinline__ void split2h(float v, __half& hi, __half& lo) {
    hi = __float2half_rn(v);
    lo = __float2half_rn(v - __half2float(hi));
}
__device__ __forceinline__ uint32_t packh(__half a, __half b) {
    return (uint32_t)__half_as_ushort(a) | ((uint32_t)__half_as_ushort(b) << 16);
}

// ---------------------------------------------------------------------------
// Kernel 1: x[B,D,S] + PE -> xTh single fp16 rows [B*S, 1024]
// ---------------------------------------------------------------------------
__global__ void pe_transpose_h(const float* __restrict__ x,
                               __half* __restrict__ out) {
    __shared__ float tile[32][33];
    int b = blockIdx.z;
    int d0 = blockIdx.y * 32, s0 = blockIdx.x * 32;
    int d = d0 + threadIdx.y, s = s0 + threadIdx.x;
    float denom = expf((float)(d & ~1) * (-9.210340371976184f / (float)DM));
    float ang = (float)s * denom;
    float pe = (d & 1) ? cosf(ang) : sinf(ang);
    tile[threadIdx.y][threadIdx.x] = x[((size_t)b * DM + d) * SS + s] + pe;
    __syncthreads();
    int s2 = s0 + threadIdx.y, d2 = d0 + threadIdx.x;
    out[((size_t)b * SS + s2) * DM + d2] = __float2half_rn(tile[threadIdx.x][threadIdx.y]);
}

// ---------------------------------------------------------------------------
// Kernel 1b: all four weights -> single fp16 rows
// ---------------------------------------------------------------------------
__global__ void wconv_kernel(const float* __restrict__ w0, const float* __restrict__ w1,
                             const float* __restrict__ w2, const float* __restrict__ w3,
                             __half* oqkv, __half* oo) {
    int idx = blockIdx.x * 256 + threadIdx.x;
    int which = blockIdx.y;
    if (which < 3) {
        const float* src = (which == 0) ? w0 : (which == 1) ? w1 : w2;
        oqkv[(size_t)which * DM * DM + idx] = __float2half_rn(src[idx]);
    } else {
        oo[idx] = __float2half_rn(w3[idx]);
    }
}

// ---------------------------------------------------------------------------
// Kernel 2a: 1-pass fp16 QKV GEMM.  C = a · w,  N = 3072 fused.
// Epilogues emit single-fp16 attention layouts.
// ---------------------------------------------------------------------------
#define STGQ1 20480
#define GEMM_SMEM 66048  // epilogue 128*129*4 dominates
#define QSCALE 0.18033688011112042f  // 0.125 * log2(e)

__global__ __launch_bounds__(256, 2)
void hmma_qkv(const __half* __restrict__ A, const __half* __restrict__ W,
              const float* __restrict__ bq, const float* __restrict__ bk,
              const float* __restrict__ bv,
              __half* __restrict__ outQ, __half* __restrict__ outK,
              __half* __restrict__ outV) {
    extern __shared__ char smem[];
    const uint32_t sb = smem_u32(smem);
    const int tid = threadIdx.x, wid = tid >> 5, lane = tid & 31;
    const int wr = wid >> 1, wc = wid & 1;
    const int mBase = blockIdx.y * 128, nBase = blockIdx.x * 128;

    float acc[2][8][4];
#pragma unroll
    for (int i = 0; i < 2; i++)
#pragma unroll
        for (int j = 0; j < 8; j++)
#pragma unroll
            for (int r = 0; r < 4; r++) acc[i][j][r] = 0.f;

    const int r0 = tid >> 2, c4 = tid & 3;
    const __half* gA = A + (size_t)(mBase + r0) * DM + c4 * 8;
    const __half* gW = W + (size_t)(nBase + r0) * DM + c4 * 8;

#define LOAD_CHUNKQ(c, st)                                                    \
    do {                                                                      \
        uint32_t s0 = sb + (st) * STGQ1 + r0 * 80 + c4 * 16;                  \
        cp16(s0,                 gA + (c) * 32);                              \
        cp16(s0 + 64 * 80,       gA + (size_t)64 * DM + (c) * 32);            \
        cp16(s0 + 10240,         gW + (c) * 32);                              \
        cp16(s0 + 10240 + 64*80, gW + (size_t)64 * DM + (c) * 32);            \
        CP_COMMIT();                                                          \
    } while (0)

    LOAD_CHUNKQ(0, 0);
    LOAD_CHUNKQ(1, 1);

    const uint32_t aB = (wr * 32 + (lane & 15)) * 80 + (lane >> 4) * 16;
    const uint32_t bB = 10240 + (wc * 64 + (lane & 15)) * 80 + (lane >> 4) * 16;

    const int NCH = 1024 / 32;  // 32
    for (int c = 0; c < NCH; c++) {
        if (c == NCH - 1) CP_WAIT0(); else CP_WAIT1();
        __syncthreads();
        const uint32_t stg = sb + (c & 1) * STGQ1;
#pragma unroll
        for (int ks = 0; ks < 2; ks++) {
            uint32_t a[2][4], bw[4][4];
            ldsm4(a[0], stg + aB + ks * 32);
            ldsm4(a[1], stg + aB + 16 * 80 + ks * 32);
#pragma unroll
            for (int j2 = 0; j2 < 4; j2++)
                ldsm4(bw[j2], stg + bB + j2 * 16 * 80 + ks * 32);
#pragma unroll
            for (int mi = 0; mi < 2; mi++)
#pragma unroll
                for (int nj = 0; nj < 8; nj++)
                    mma16816h(acc[mi][nj], a[mi],
                              bw[nj >> 1][nj & 1], bw[nj >> 1][(nj & 1) + 2]);
        }
        __syncthreads();
        if (c + 2 < NCH) LOAD_CHUNKQ(c + 2, c & 1);
    }
#undef LOAD_CHUNKQ

    __syncthreads();
    float* ep = (float*)smem;
#pragma unroll
    for (int mi = 0; mi < 2; mi++)
#pragma unroll
        for (int nj = 0; nj < 8; nj++) {
            int row = wr * 32 + mi * 16 + (lane >> 2);
            int col = wc * 64 + nj * 8 + (lane & 3) * 2;
            ep[row * 129 + col] = acc[mi][nj][0];
            ep[row * 129 + col + 1] = acc[mi][nj][1];
            ep[(row + 8) * 129 + col] = acc[mi][nj][2];
            ep[(row + 8) * 129 + col + 1] = acc[mi][nj][3];
        }
    __syncthreads();

    if (nBase >= 2048) {
        // V^T: [bh, chunk, d, 64] fp16; coalesced uint4 stores.
        int b = mBase >> 11, s0 = mBase & 2047;
#pragma unroll
        for (int it = 0; it < 8; it++) {
            int t = tid + it * 256;
            int dl = t >> 4;
            int rem = t & 15;
            int ch = rem >> 3, jb = (rem & 7) * 8;
            int n = nBase - 2048 + dl;
            int h = n >> 6, dd = n & 63;
            float bn = bv[n];
            size_t vb = (((size_t)(b * HH + h)) * 32 + (s0 >> 6) + ch) * (64 * KW)
                        + (size_t)dd * KW;
            uint32_t hp[4];
#pragma unroll
            for (int j2 = 0; j2 < 4; j2++) {
                float v0 = ep[(ch * 64 + jb + 2 * j2) * 129 + dl] + bn;
                float v1 = ep[(ch * 64 + jb + 2 * j2 + 1) * 129 + dl] + bn;
                hp[j2] = pack2h(v0, v1);
            }
            *(uint4*)&outV[vb + jb] = *(uint4*)&hp[0];
        }
    } else if (nBase >= 1024) {
        // K: rows of 64 fp16
#pragma unroll
        for (int i = 0; i < 8; i++) {
            int r = (tid >> 4) + i * 16;
            int cc = (tid & 15) * 8;
            int m = mBase + r, b = m >> 11, s = m & 2047;
            int n = nBase - 1024 + cc, h = n >> 6, dd = n & 63;
            size_t base = ((size_t)(b * HH + h) * SS + s) * KW;
            uint32_t kp[4];
#pragma unroll
            for (int j2 = 0; j2 < 4; j2++) {
                float v0 = ep[r * 129 + cc + 2 * j2] + bk[n + 2 * j2];
                float v1 = ep[r * 129 + cc + 2 * j2 + 1] + bk[n + 2 * j2 + 1];
                kp[j2] = pack2h(v0, v1);
            }
            *(uint4*)&outK[base + dd] = *(uint4*)&kp[0];
        }
    } else {
        // Q: rows of 64 fp16, xQSCALE
#pragma unroll
        for (int i = 0; i < 8; i++) {
            int r = (tid >> 4) + i * 16;
            int cc = (tid & 15) * 8;
            int m = mBase + r, b = m >> 11, s = m & 2047;
            int n = nBase + cc, h = n >> 6, dd = n & 63;
            size_t base = ((size_t)(b * HH + h) * SS + s) * QW;
            uint32_t qp[4];
#pragma unroll
            for (int j2 = 0; j2 < 4; j2++) {
                float v0 = (ep[r * 129 + cc + 2 * j2] + bq[n + 2 * j2]) * QSCALE;
                float v1 = (ep[r * 129 + cc + 2 * j2 + 1] + bq[n + 2 * j2 + 1]) * QSCALE;
                qp[j2] = pack2h(v0, v1);
            }
            *(uint4*)&outQ[base + dd] = *(uint4*)&qp[0];
        }
    }
}

// ---------------------------------------------------------------------------
// Kernel 2b: 2-pass fp16 output GEMM.  C = (ah + al) · w -> fp32 [B,D,S].
// ---------------------------------------------------------------------------
#define STGO 30720

__global__ __launch_bounds__(256, 2)
void hmma_out(const __half* __restrict__ A, const __half* __restrict__ W,
              const float* __restrict__ bias, float* __restrict__ out) {
    extern __shared__ char smem[];
    const uint32_t sb = smem_u32(smem);
    const int tid = threadIdx.x, wid = tid >> 5, lane = tid & 31;
    const int wr = wid >> 1, wc = wid & 1;
    const int mBase = blockIdx.y * 128, nBase = blockIdx.x * 128;

    float acc[2][8][4];
#pragma unroll
    for (int i = 0; i < 2; i++)
#pragma unroll
        for (int j = 0; j < 8; j++)
#pragma unroll
            for (int r = 0; r < 4; r++) acc[i][j][r] = 0.f;

    const int r0 = tid >> 2, c4 = tid & 3;
    const __half* gA = A + (size_t)(mBase + r0) * K2 + c4 * 8;
    const __half* gW = W + (size_t)(nBase + r0) * DM + c4 * 8;

#define LOAD_CHUNKO(c, st)                                                    \
    do {                                                                      \
        uint32_t s0 = sb + (st) * STGO + r0 * 80 + c4 * 16;                   \
        cp16(s0,                 gA + (c) * 32);                              \
        cp16(s0 + 64 * 80,       gA + (size_t)64 * K2 + (c) * 32);            \
        cp16(s0 + 10240,         gA + 1024 + (c) * 32);                       \
        cp16(s0 + 10240 + 64*80, gA + (size_t)64 * K2 + 1024 + (c) * 32);     \
        cp16(s0 + 20480,         gW + (c) * 32);                              \
        cp16(s0 + 20480 + 64*80, gW + (size_t)64 * DM + (c) * 32);            \
        CP_COMMIT();                                                          \
    } while (0)

    LOAD_CHUNKO(0, 0);
    LOAD_CHUNKO(1, 1);

    const uint32_t aB = (wr * 32 + (lane & 15)) * 80 + (lane >> 4) * 16;
    const uint32_t bB = 20480 + (wc * 64 + (lane & 15)) * 80 + (lane >> 4) * 16;

    const int NCH = 1024 / 32;
    for (int c = 0; c < NCH; c++) {
        if (c == NCH - 1) CP_WAIT0(); else CP_WAIT1();
        __syncthreads();
        const uint32_t stg = sb + (c & 1) * STGO;
#pragma unroll
        for (int ks = 0; ks < 2; ks++) {
            uint32_t ah[2][4], al[2][4], bw[4][4];
            ldsm4(ah[0], stg + aB + ks * 32);
            ldsm4(ah[1], stg + aB + 16 * 80 + ks * 32);
            ldsm4(al[0], stg + aB + 10240 + ks * 32);
            ldsm4(al[1], stg + aB + 10240 + 16 * 80 + ks * 32);
#pragma unroll
            for (int j2 = 0; j2 < 4; j2++)
                ldsm4(bw[j2], stg + bB + j2 * 16 * 80 + ks * 32);
#pragma unroll
            for (int mi = 0; mi < 2; mi++)
#pragma unroll
                for (int nj = 0; nj < 8; nj++) {
                    uint32_t b0 = bw[nj >> 1][nj & 1], b1 = bw[nj >> 1][(nj & 1) + 2];
                    mma16816h(acc[mi][nj], ah[mi], b0, b1);
                    mma16816h(acc[mi][nj], al[mi], b0, b1);
                }
        }
        __syncthreads();
        if (c + 2 < NCH) LOAD_CHUNKO(c + 2, c & 1);
    }
#undef LOAD_CHUNKO

    __syncthreads();
    float* ep = (float*)smem;
#pragma unroll
    for (int mi = 0; mi < 2; mi++)
#pragma unroll
        for (int nj = 0; nj < 8; nj++) {
            int row = wr * 32 + mi * 16 + (lane >> 2);
            int col = wc * 64 + nj * 8 + (lane & 3) * 2;
            ep[row * 129 + col] = acc[mi][nj][0];
            ep[row * 129 + col + 1] = acc[mi][nj][1];
            ep[(row + 8) * 129 + col] = acc[mi][nj][2];
            ep[(row + 8) * 129 + col + 1] = acc[mi][nj][3];
        }
    __syncthreads();

    int nl = tid >> 1;
    int n = nBase + nl;
    float bn = bias[n];
#pragma unroll
    for (int ii = 0; ii < 16; ii++) {
        int sl = (tid & 1) * 64 + ii * 4;
        int m0 = mBase + sl, b = m0 >> 11, s = m0 & 2047;
        float4 v;
        v.x = ep[(sl + 0) * 129 + nl] + bn;
        v.y = ep[(sl + 1) * 129 + nl] + bn;
        v.z = ep[(sl + 2) * 129 + nl] + bn;
        v.w = ep[(sl + 3) * 129 + nl] + bn;
        *(float4*)&out[((size_t)b * DM + n) * SS + s] = v;
    }
}

// ---------------------------------------------------------------------------
// Kernel 3: fp16 flash attention, single-precision K/V (2 MMA passes/iter).
// CTA = (b,h) x 128 q; 8 warps x 16q; 2-stage KV ring; base-2 softmax.
// ---------------------------------------------------------------------------
#define QPITCH 144
#define AQSZ (128 * QPITCH)          // 18432
#define KVPITCH 144
#define AKVT (64 * KVPITCH)          // 9216 per K (or V) tile
#define ASTG (2 * AKVT)              // 18432 per stage
#define ATTN_SMEM (AQSZ + 2 * ASTG)  // 55296

__device__ __forceinline__ void load_kv(uint32_t sb, int tid,
                                        const __half* Kg, const __half* Vg,
                                        int kt, int st) {
#pragma unroll
    for (int i = 0; i < 4; i++) {
        int idx = tid + i * 256;           // 0..1023
        int t = idx >= 512;                // 0 = K, 1 = V
        int j = idx - t * 512;
        int r = j >> 3, seg = j & 7;       // 8 segs of 16B = 128B/row
        uint32_t so = AQSZ + st * ASTG + t * AKVT + r * KVPITCH + seg * 16;
        size_t go = ((size_t)kt * 64 + r) * KW + seg * 8;
        cp16(sb + so, (t ? Vg : Kg) + go);
    }
    CP_COMMIT();
}

__global__ __launch_bounds__(256, 2)
void attn_hmma(const __half* __restrict__ Qs, const __half* __restrict__ Ks,
               const __half* __restrict__ Vt, __half* __restrict__ O) {
    extern __shared__ char smem[];
    const uint32_t sb = smem_u32(smem);
    const int tid = threadIdx.x, w = tid >> 5, lane = tid & 31;
    const int bh = blockIdx.y;
    const int q0 = blockIdx.x * 128;
    const __half* Qg = Qs + ((size_t)bh * SS + q0) * QW;
    const __half* Kg = Ks + (size_t)bh * SS * KW;
    const __half* Vg = Vt + (size_t)bh * (32 * 64 * KW);

#pragma unroll
    for (int i = 0; i < 4; i++) {
        int idx = tid + i * 256;
        int row = idx >> 3, seg = idx & 7;
        cp16(sb + row * QPITCH + seg * 16, Qg + (size_t)row * QW + seg * 8);
    }
    load_kv(sb, tid, Kg, Vg, 0, 0);
    load_kv(sb, tid, Kg, Vg, 1, 1);

    float o[8][4];
    float mi[2] = {-1e30f, -1e30f}, li[2] = {0.f, 0.f};
#pragma unroll
    for (int nj = 0; nj < 8; nj++)
#pragma unroll
        for (int r = 0; r < 4; r++) o[nj][r] = 0.f;

    const int q4 = lane & 3;
    const int r1 = w * 16 + (lane >> 2);
    const uint32_t aQ = sb + (w * 16 + (lane & 15)) * QPITCH + (lane >> 4) * 16;
    const uint32_t bKb = sb + AQSZ + (lane & 15) * KVPITCH + (lane >> 4) * 16;

    for (int kt = 0; kt < 32; kt++) {
        if (kt == 31) CP_WAIT0(); else CP_WAIT1();
        __syncthreads();
        const uint32_t stoff = (kt & 1) * ASTG;

        // --- S = qf · kf (single pass) ---
        float sc[8][4];
#pragma unroll
        for (int nj = 0; nj < 8; nj++)
#pragma unroll
            for (int r = 0; r < 4; r++) sc[nj][r] = 0.f;
#pragma unroll
        for (int ks = 0; ks < 4; ks++) {
            uint32_t aq[4], bk4[4][4];
            ldsm4(aq, aQ + ks * 32);
#pragma unroll
            for (int j2 = 0; j2 < 4; j2++)
                ldsm4(bk4[j2], bKb + stoff + j2 * 16 * KVPITCH + ks * 32);
#pragma unroll
            for (int nj = 0; nj < 8; nj++)
                mma16816h(sc[nj], aq, bk4[nj >> 1][nj & 1], bk4[nj >> 1][(nj & 1) + 2]);
        }

        // --- base-2 online softmax; P -> fp16 register A-fragments ---
        uint32_t aPf[4][4];
#pragma unroll
        for (int rr = 0; rr < 2; rr++) {
            float mx = -1e30f;
#pragma unroll
            for (int nj = 0; nj < 8; nj++)
                mx = fmaxf(mx, fmaxf(sc[nj][rr * 2], sc[nj][rr * 2 + 1]));
            mx = fmaxf(mx, __shfl_xor_sync(0xffffffffu, mx, 1));
            mx = fmaxf(mx, __shfl_xor_sync(0xffffffffu, mx, 2));
            float mn = fmaxf(mi[rr], mx);
            float rs = 0.f;
#pragma unroll
            for (int nj = 0; nj < 8; nj++) {
                float p0 = ex2(sc[nj][rr * 2] - mn);
                float p1 = ex2(sc[nj][rr * 2 + 1] - mn);
                rs += p0 + p1;
                aPf[nj >> 1][(nj & 1) * 2 + rr] = pack2h(p0, p1);
            }
            rs += __shfl_xor_sync(0xffffffffu, rs, 1);
            rs += __shfl_xor_sync(0xffffffffu, rs, 2);
            float f = ex2(mi[rr] - mn);
            li[rr] = li[rr] * f + rs;
            mi[rr] = mn;
#pragma unroll
            for (int nj = 0; nj < 8; nj++) {
                o[nj][rr * 2] *= f;
                o[nj][rr * 2 + 1] *= f;
            }
        }

        // --- O += Pf · vf (single pass) ---
        const uint32_t bVb = bKb + AKVT + stoff;
#pragma unroll
        for (int kk = 0; kk < 4; kk++) {
            uint32_t bv4[4][4];
#pragma unroll
            for (int j2 = 0; j2 < 4; j2++)
                ldsm4(bv4[j2], bVb + j2 * 16 * KVPITCH + kk * 32);
#pragma unroll
            for (int nj = 0; nj < 8; nj++)
                mma16816h(o[nj], aPf[kk], bv4[nj >> 1][nj & 1], bv4[nj >> 1][(nj & 1) + 2]);
        }
        __syncthreads();
        if (kt + 2 < 32) load_kv(sb, tid, Kg, Vg, kt + 2, kt & 1);
    }

    // epilogue: normalize, emit fp16 [ah|al] rows for Wo GEMM
    const int b_ = bh >> 4, h_ = bh & 15;
#pragma unroll
    for (int rr = 0; rr < 2; rr++) {
        float inv = 1.f / li[rr];
        size_t base = ((size_t)b_ * SS + q0 + r1 + rr * 8) * (size_t)K2;
#pragma unroll
        for (int nj = 0; nj < 8; nj++) {
            int d = nj * 8 + 2 * q4;
            float v0 = o[nj][rr * 2] * inv, v1 = o[nj][rr * 2 + 1] * inv;
            __half h0, l0, h1, l1;
            split2h(v0, h0, l0); split2h(v1, h1, l1);
            *(uint32_t*)&O[base + h_ * 64 + d] = packh(h0, h1);
            *(uint32_t*)&O[base + 1024 + h_ * 64 + d] = packh(l0, l1);
        }
    }
}

// ---------------------------------------------------------------------------
extern "C" void kernel_launch(void* const* d_in, const int* in_sizes, int n_in,
                              void* d_out, int out_size) {
    const float* x  = (const float*)d_in[0];
    const float* Wq = (const float*)d_in[1];
    const float* bq = (const float*)d_in[2];
    const float* Wk = (const float*)d_in[3];
    const float* bk = (const float*)d_in[4];
    const float* Wv = (const float*)d_in[5];
    const float* bv = (const float*)d_in[6];
    const float* Wo = (const float*)d_in[7];
    const float* bo = (const float*)d_in[8];

    __half *xTh, *wqkv, *wo1, *qs, *ks, *vt, *attb;
    cudaGetSymbolAddress((void**)&xTh, g_xTh);
    cudaGetSymbolAddress((void**)&wqkv, g_Wqkv);
    cudaGetSymbolAddress((void**)&wo1, g_Wo1);
    cudaGetSymbolAddress((void**)&qs, g_Qs);
    cudaGetSymbolAddress((void**)&ks, g_Ks);
    cudaGetSymbolAddress((void**)&vt, g_Vt);
    cudaGetSymbolAddress((void**)&attb, g_attbig);

    pe_transpose_h<<<dim3(SS / 32, DM / 32, BB), dim3(32, 32)>>>(x, xTh);
    wconv_kernel<<<dim3(DM * DM / 256, 4), 256>>>(Wq, Wk, Wv, Wo, wqkv, wo1);

    cudaFuncSetAttribute(hmma_qkv, cudaFuncAttributeMaxDynamicSharedMemorySize, GEMM_SMEM);
    cudaFuncSetAttribute(hmma_out, cudaFuncAttributeMaxDynamicSharedMemorySize, GEMM_SMEM);
    dim3 ggQKV(3 * DM / 128, (BB * SS) / 128);  // (24, 64)
    dim3 gg(DM / 128, (BB * SS) / 128);         // (8, 64)
    hmma_qkv<<<ggQKV, 256, GEMM_SMEM>>>(xTh, wqkv, bq, bk, bv, qs, ks, vt);

    cudaFuncSetAttribute(attn_hmma, cudaFuncAttributeMaxDynamicSharedMemorySize, ATTN_SMEM);
    attn_hmma<<<dim3(SS / 128, BB * HH), 256, ATTN_SMEM>>>(qs, ks, vt, attb);

    hmma_out<<<gg, 256, GEMM_SMEM>>>(attb, wo1, bo, (float*)d_out);
}